// round 1
// baseline (speedup 1.0000x reference)
#include <cuda_runtime.h>

#define B_ 8
#define N_ 1024
#define H_ 768
#define NH_ 12
#define M_ 256

// ---------------- scratch (device globals; no allocation) ----------------
__device__ float g_var_in[B_*N_*H_];
__device__ float g_varfeat[B_*N_*H_];
__device__ float g_symfeat[B_*N_*H_];
__device__ float g_Qb[B_*N_*H_];
__device__ float g_Kb[B_*N_*H_];
__device__ float g_Vb[B_*N_*H_];
__device__ float g_Sb[(size_t)B_*NH_*N_*N_];   // 402 MB attention logits
__device__ float g_sc[B_*N_];
__device__ float g_vg2[B_*N_];
__device__ float g_ab[B_*N_];
__device__ float g_dg[B_*N_];
__device__ float g_wt[B_*N_];
__device__ float g_sumw[B_];
__device__ float g_c1[B_*N_];
__device__ float g_c2[B_*N_];
__device__ float g_r1[B_*NH_*N_];
__device__ float g_r2[B_*NH_*N_];
__device__ float g_A1[B_*H_];
__device__ float g_A2[B_*H_];
__device__ float g_pm[B_*H_];

__device__ __forceinline__ bool d_pred(const int* P, int i){ return P[i]==1; }
__device__ __forceinline__ bool d_single(const int* P, int i){ return (i==0) || (i>=2 && P[i-2]==1); }

// ---------------- init: zero accumulators ----------------
__global__ void k_init(){
  int i = blockIdx.x*blockDim.x + threadIdx.x;
  if (i < B_*N_) g_vg2[i] = 0.f;
  if (i < B_*NH_*N_){ g_r1[i]=0.f; g_r2[i]=0.f; }
  if (i < B_*H_){ g_A1[i]=0.f; g_A2[i]=0.f; }
}

// ---------------- var_in (rolled neighbor average) ----------------
__global__ void k_varin(const float* __restrict__ x, const int* __restrict__ pp){
  int idx = blockIdx.x*blockDim.x + threadIdx.x;
  if (idx >= B_*N_*H_) return;
  int hh = idx % H_;
  int n  = (idx / H_) % N_;
  int b  = idx / (N_*H_);
  bool single = (n==0) || (n>=2 && pp[b*N_+n-2]==1);
  int np = (n+1)&(N_-1);
  int nm = (n+N_-1)&(N_-1);
  float xn = x[((size_t)b*N_+np)*H_+hh];
  float v = single ? xn : 0.5f*(x[((size_t)b*N_+nm)*H_+hh] + xn);
  g_var_in[idx] = v;
}

// ---------------- SGEMM: C[m,n] = alpha*(sum_k A[m,k]*W[n,k] + bias[n]) ----------------
// A: [8192, 768] lda=768; W: [768, 768] ldb=768; C: ldc=768. 128x128x8 tile, 256 thr, 8x8/thread.
__global__ __launch_bounds__(256) void k_gemm_proj(const float* __restrict__ A,
                                                   const float* __restrict__ W,
                                                   const float* __restrict__ bias,
                                                   float* __restrict__ C, float alpha){
  __shared__ float As[8][128], Bs[8][128];
  int tid = threadIdx.x;
  int m0 = blockIdx.y*128, n0 = blockIdx.x*128;
  int lrow = tid>>1, lcol = (tid&1)*4;
  int tx = tid&15, ty = tid>>4;
  float acc[8][8] = {};
  const float* Ap = A + (size_t)(m0+lrow)*H_ + lcol;
  const float* Wp = W + (size_t)(n0+lrow)*H_ + lcol;
  for (int k0=0; k0<H_; k0+=8){
    float4 av = *(const float4*)(Ap + k0);
    float4 bv = *(const float4*)(Wp + k0);
    As[lcol+0][lrow]=av.x; As[lcol+1][lrow]=av.y; As[lcol+2][lrow]=av.z; As[lcol+3][lrow]=av.w;
    Bs[lcol+0][lrow]=bv.x; Bs[lcol+1][lrow]=bv.y; Bs[lcol+2][lrow]=bv.z; Bs[lcol+3][lrow]=bv.w;
    __syncthreads();
    #pragma unroll
    for (int k=0;k<8;k++){
      float ra[8], rb[8];
      *(float4*)ra     = *(const float4*)&As[k][ty*8];
      *(float4*)(ra+4) = *(const float4*)&As[k][ty*8+4];
      *(float4*)rb     = *(const float4*)&Bs[k][tx*8];
      *(float4*)(rb+4) = *(const float4*)&Bs[k][tx*8+4];
      #pragma unroll
      for (int i=0;i<8;i++)
        #pragma unroll
        for (int j=0;j<8;j++) acc[i][j] += ra[i]*rb[j];
    }
    __syncthreads();
  }
  #pragma unroll
  for (int i=0;i<8;i++){
    int m = m0 + ty*8 + i;
    #pragma unroll
    for (int j=0;j<8;j++){
      int nn = n0 + tx*8 + j;
      C[(size_t)m*H_ + nn] = alpha*(acc[i][j] + bias[nn]);
    }
  }
}

// ---------------- batched QK^T : S[z] = Q_h K_h^T (Q pre-scaled) ----------------
__global__ __launch_bounds__(256) void k_gemm_qk(){
  int z = blockIdx.z, b = z/NH_, h = z - b*NH_;
  const float* A = g_Qb + (size_t)b*N_*H_ + h*64;
  const float* W = g_Kb + (size_t)b*N_*H_ + h*64;
  float* C = g_Sb + (size_t)z*N_*N_;
  __shared__ float As[8][128], Bs[8][128];
  int tid = threadIdx.x;
  int m0 = blockIdx.y*128, n0 = blockIdx.x*128;
  int lrow = tid>>1, lcol = (tid&1)*4;
  int tx = tid&15, ty = tid>>4;
  float acc[8][8] = {};
  const float* Ap = A + (size_t)(m0+lrow)*H_ + lcol;
  const float* Wp = W + (size_t)(n0+lrow)*H_ + lcol;
  for (int k0=0; k0<64; k0+=8){
    float4 av = *(const float4*)(Ap + k0);
    float4 bv = *(const float4*)(Wp + k0);
    As[lcol+0][lrow]=av.x; As[lcol+1][lrow]=av.y; As[lcol+2][lrow]=av.z; As[lcol+3][lrow]=av.w;
    Bs[lcol+0][lrow]=bv.x; Bs[lcol+1][lrow]=bv.y; Bs[lcol+2][lrow]=bv.z; Bs[lcol+3][lrow]=bv.w;
    __syncthreads();
    #pragma unroll
    for (int k=0;k<8;k++){
      float ra[8], rb[8];
      *(float4*)ra     = *(const float4*)&As[k][ty*8];
      *(float4*)(ra+4) = *(const float4*)&As[k][ty*8+4];
      *(float4*)rb     = *(const float4*)&Bs[k][tx*8];
      *(float4*)(rb+4) = *(const float4*)&Bs[k][tx*8+4];
      #pragma unroll
      for (int i=0;i<8;i++)
        #pragma unroll
        for (int j=0;j<8;j++) acc[i][j] += ra[i]*rb[j];
    }
    __syncthreads();
  }
  #pragma unroll
  for (int i=0;i<8;i++){
    int m = m0 + ty*8 + i;
    #pragma unroll
    for (int j=0;j<8;j++)
      C[(size_t)m*N_ + n0 + tx*8 + j] = acc[i][j];
  }
}

// ---------------- edge score s = lrelu(tanh(varfeat).ws_lo + tanh(symfeat).ws_hi + b) ----------------
__global__ __launch_bounds__(256) void k_score(const float* __restrict__ Wsc, const float* __restrict__ bsc){
  int row = blockIdx.x;             // b*N + n
  size_t base = (size_t)row * H_;
  float p = 0.f;
  for (int h = threadIdx.x; h < H_; h += 256)
    p += tanhf(g_varfeat[base+h])*Wsc[h] + tanhf(g_symfeat[base+h])*Wsc[H_+h];
  for (int o=16;o;o>>=1) p += __shfl_xor_sync(0xffffffffu, p, o);
  __shared__ float red[8];
  if ((threadIdx.x&31)==0) red[threadIdx.x>>5] = p;
  __syncthreads();
  if (threadIdx.x==0){
    float t = bsc[0];
    #pragma unroll
    for (int i=0;i<8;i++) t += red[i];
    g_sc[row] = t >= 0.f ? t : 0.02f*t;
  }
}

// ---------------- cross scores -> VG^2 diagonal ----------------
__global__ __launch_bounds__(128) void k_cross(const float* __restrict__ x, const float* __restrict__ Wc,
                                               const float* __restrict__ bc, const int* __restrict__ occ){
  int pid = blockIdx.x;             // b*M + j
  int b = pid / M_;
  int o0 = occ[pid*2], o1 = occ[pid*2+1];
  const float* x0 = x + ((size_t)b*N_+o0)*H_;
  const float* x1 = x + ((size_t)b*N_+o1)*H_;
  float p = 0.f;
  for (int h=threadIdx.x; h<H_; h+=128) p += 0.5f*(x0[h]+x1[h])*Wc[h];
  for (int o=16;o;o>>=1) p += __shfl_xor_sync(0xffffffffu, p, o);
  __shared__ float red[4];
  if ((threadIdx.x&31)==0) red[threadIdx.x>>5] = p;
  __syncthreads();
  if (threadIdx.x==0){
    float t = bc[0] + red[0]+red[1]+red[2]+red[3];
    t = t >= 0.f ? t : 0.02f*t;
    atomicAdd(&g_vg2[b*N_+o0], t*t);
    atomicAdd(&g_vg2[b*N_+o1], t*t);
  }
}

// ---------------- AG band a_r, node weights w ----------------
__global__ void k_band(const int* __restrict__ pp){
  int idx = blockIdx.x*blockDim.x + threadIdx.x;
  if (idx >= B_*N_) return;
  int b = idx >> 10, n = idx & (N_-1);
  const int* P = pp + b*N_;
  const float* s = g_sc + b*N_;
  float a = 0.f;
  if (n < N_-1){
    float sl1 = d_pred(P,n+1) ? s[n+1] : 0.f;                       // lower: pred & i>=1 (i=n+1>=1)
    bool up0 = d_pred(P,n) && (n<=1 || !d_single(P,n));
    float su0 = up0 ? s[n] : 0.f;
    a = sl1 + su0;
  }
  g_ab[idx] = a;
  bool up = d_pred(P,n) && (n<=1 || !d_single(P,n));
  bool tr = up && (n>=1);
  g_wt[idx] = d_pred(P,n) ? (tr?3.f:2.f) : 0.f;
}

__global__ __launch_bounds__(1024) void k_sumw(){
  int b = blockIdx.x;
  float v = g_wt[b*N_ + threadIdx.x];
  for (int o=16;o;o>>=1) v += __shfl_xor_sync(0xffffffffu, v, o);
  __shared__ float red[32];
  if ((threadIdx.x&31)==0) red[threadIdx.x>>5] = v;
  __syncthreads();
  if (threadIdx.x < 32){
    float t = red[threadIdx.x];
    for (int o=16;o;o>>=1) t += __shfl_xor_sync(0xffffffffu, t, o);
    if (threadIdx.x==0) g_sumw[b] = t;
  }
}

// ---------------- diag bias + output row-weights c1,c2 ----------------
__global__ void k_coef(const int* __restrict__ pp){
  int idx = blockIdx.x*blockDim.x + threadIdx.x;
  if (idx >= B_*N_) return;
  int b = idx >> 10, n = idx & (N_-1);
  const int* P = pp + b*N_;
  float am1 = (n>=1) ? g_ab[b*N_+n-1] : 0.f;
  float an = g_ab[idx];
  g_dg[idx] = 0.8f*(am1*am1 + an*an) + g_vg2[idx];
  float sw = g_sumw[b];
  int nm = (n+N_-1)&(N_-1), np = (n+1)&(N_-1);
  float c1 = g_wt[b*N_+nm]*(d_single(P,nm)?1.f:0.5f)
           + g_wt[b*N_+np]*(d_single(P,np)?0.f:0.5f);
  g_c1[idx] = c1 / sw;
  g_c2[idx] = g_wt[idx] / sw;
}

// ---------------- softmax rows + weighted column accumulation ----------------
// grid (B*NH, N/16), 512 threads: warp = one row held entirely in registers (exp once).
__global__ __launch_bounds__(512) void k_softmax(){
  int bh = blockIdx.x, b = bh / NH_;
  int warp = threadIdx.x >> 5, lane = threadIdx.x & 31;
  int n = blockIdx.y*16 + warp;
  __shared__ float r1s[N_], r2s[N_];
  for (int i=threadIdx.x; i<N_; i+=512){ r1s[i]=0.f; r2s[i]=0.f; }
  __syncthreads();
  const float* row = g_Sb + ((size_t)bh*N_ + n)*N_;
  const float* ab = g_ab + b*N_;
  float g1w = g_c1[b*N_+n], g2w = g_c2[b*N_+n];
  float v[32];
  float sum = 0.f;
  #pragma unroll
  for (int j=0;j<32;j++){
    int m = j*32 + lane;
    float xv = row[m];
    int d = m - n;
    if (d==0)       xv += g_dg[b*N_+n];
    else if (d==1)  xv += 0.2f*ab[n];
    else if (d==-1) xv += 0.2f*ab[n-1];
    else if (d==2)  xv += 0.8f*ab[n]*ab[n+1];
    else if (d==-2) xv += 0.8f*ab[n-2]*ab[n-1];
    xv = __expf(xv);
    v[j] = xv; sum += xv;
  }
  for (int o=16;o;o>>=1) sum += __shfl_xor_sync(0xffffffffu, sum, o);
  if (g1w != 0.f || g2w != 0.f){
    float inv = 1.f/sum;
    float g1 = g1w*inv, g2 = g2w*inv;
    #pragma unroll
    for (int j=0;j<32;j++){
      int m = j*32 + lane;
      atomicAdd(&r1s[m], g1*v[j]);
      atomicAdd(&r2s[m], g2*v[j]);
    }
  }
  __syncthreads();
  for (int i=threadIdx.x; i<N_; i+=512){
    atomicAdd(&g_r1[(size_t)bh*N_+i], r1s[i]);
    atomicAdd(&g_r2[(size_t)bh*N_+i], r2s[i]);
  }
}

// ---------------- A = rho @ V (per batch, concat heads) ----------------
__global__ __launch_bounds__(768) void k_matvec(){
  int b = blockIdx.x, f = threadIdx.x, h = f >> 6;
  int m0 = blockIdx.y*64;
  const float* r1 = g_r1 + ((size_t)b*NH_+h)*N_;
  const float* r2 = g_r2 + ((size_t)b*NH_+h)*N_;
  float a1=0.f, a2=0.f;
  for (int m=m0; m<m0+64; m++){
    float vv = g_Vb[((size_t)b*N_+m)*H_+f];
    a1 += r1[m]*vv; a2 += r2[m]*vv;
  }
  atomicAdd(&g_A1[b*H_+f], a1);
  atomicAdd(&g_A2[b*H_+f], a2);
}

// ---------------- u = Wo.A + bo ; pm = Watom.[u1;u2] + batom ----------------
__global__ __launch_bounds__(768) void k_final(const float* __restrict__ Wo, const float* __restrict__ bo,
                                               const float* __restrict__ Wa, const float* __restrict__ ba){
  int b = blockIdx.x, o = threadIdx.x;
  __shared__ float u1s[H_], u2s[H_];
  const float* w = Wo + (size_t)o*H_;
  const float* A1 = g_A1 + b*H_;
  const float* A2 = g_A2 + b*H_;
  float u1 = bo[o], u2 = bo[o];
  for (int i=0;i<H_;i++){ u1 += w[i]*A1[i]; u2 += w[i]*A2[i]; }
  u1s[o] = u1; u2s[o] = u2;
  __syncthreads();
  const float* wa = Wa + (size_t)o*2*H_;
  float p = ba[o];
  for (int i=0;i<H_;i++) p += wa[i]*u1s[i] + wa[H_+i]*u2s[i];
  g_pm[b*H_+o] = p;
}

__global__ void k_bcast(float* __restrict__ out){
  int idx = blockIdx.x*blockDim.x + threadIdx.x;
  if (idx >= B_*N_*H_) return;
  int f = idx % H_;
  int b = idx / (N_*H_);
  out[idx] = g_pm[b*H_+f];
}

// ---------------- launch ----------------
extern "C" void kernel_launch(void* const* d_in, const int* in_sizes, int n_in,
                              void* d_out, int out_size){
  (void)in_sizes; (void)n_in; (void)out_size;
  const float* x      = (const float*)d_in[0];
  const float* W_var  = (const float*)d_in[3];
  const float* b_var  = (const float*)d_in[4];
  const float* W_sym  = (const float*)d_in[5];
  const float* b_sym  = (const float*)d_in[6];
  const float* W_sc   = (const float*)d_in[7];
  const float* b_scb  = (const float*)d_in[8];
  const float* W_cr   = (const float*)d_in[9];
  const float* b_cr   = (const float*)d_in[10];
  const float* W_atom = (const float*)d_in[11];
  const float* b_atom = (const float*)d_in[12];
  const float* W_q    = (const float*)d_in[13];
  const float* b_q    = (const float*)d_in[14];
  const float* W_k    = (const float*)d_in[15];
  const float* b_k    = (const float*)d_in[16];
  const float* W_v    = (const float*)d_in[17];
  const float* b_v    = (const float*)d_in[18];
  const float* W_o    = (const float*)d_in[19];
  const float* b_o    = (const float*)d_in[20];
  const int*   pp     = (const int*)d_in[21];
  const int*   occ    = (const int*)d_in[24];
  float* out = (float*)d_out;

  float *p_varin, *p_varfeat, *p_symfeat, *p_Q, *p_K, *p_V;
  cudaGetSymbolAddress((void**)&p_varin,   g_var_in);
  cudaGetSymbolAddress((void**)&p_varfeat, g_varfeat);
  cudaGetSymbolAddress((void**)&p_symfeat, g_symfeat);
  cudaGetSymbolAddress((void**)&p_Q,       g_Qb);
  cudaGetSymbolAddress((void**)&p_K,       g_Kb);
  cudaGetSymbolAddress((void**)&p_V,       g_Vb);

  k_init<<<(B_*NH_*N_+255)/256, 256>>>();
  k_varin<<<(B_*N_*H_+255)/256, 256>>>(x, pp);

  dim3 gp(H_/128, (B_*N_)/128);
  k_gemm_proj<<<gp,256>>>(p_varin, W_var, b_var, p_varfeat, 1.f);
  k_gemm_proj<<<gp,256>>>(x,       W_sym, b_sym, p_symfeat, 1.f);
  k_gemm_proj<<<gp,256>>>(x,       W_q,   b_q,   p_Q, 0.125f);  // SCALE folded in
  k_gemm_proj<<<gp,256>>>(x,       W_k,   b_k,   p_K, 1.f);
  k_gemm_proj<<<gp,256>>>(x,       W_v,   b_v,   p_V, 1.f);

  k_score<<<B_*N_, 256>>>(W_sc, b_scb);
  k_cross<<<B_*M_, 128>>>(x, W_cr, b_cr, occ);
  k_band<<<(B_*N_+255)/256, 256>>>(pp);
  k_sumw<<<B_, 1024>>>();
  k_coef<<<(B_*N_+255)/256, 256>>>(pp);

  dim3 gqk(N_/128, N_/128, B_*NH_);
  k_gemm_qk<<<gqk, 256>>>();

  dim3 gsm(B_*NH_, N_/16);
  k_softmax<<<gsm, 512>>>();

  dim3 gmv(B_, 16);
  k_matvec<<<gmv, 768>>>();
  k_final<<<B_, 768>>>(W_o, b_o, W_atom, b_atom);
  k_bcast<<<(B_*N_*H_+255)/256, 256>>>(out);
}

// round 2
// speedup vs baseline: 1.3598x; 1.3598x over previous
#include <cuda_runtime.h>
#include <mma.h>
using namespace nvcuda;

#define B_ 8
#define N_ 1024
#define H_ 768
#define NH_ 12
#define M_ 256

// ---------------- scratch (device globals; no allocation) ----------------
__device__ float g_var_in[B_*N_*H_];
__device__ float g_varfeat[B_*N_*H_];
__device__ float g_symfeat[B_*N_*H_];
__device__ float g_Qb[B_*N_*H_];
__device__ float g_Kb[B_*N_*H_];
__device__ float g_Vb[B_*N_*H_];
__device__ float g_sc[B_*N_];
__device__ float g_vg2[B_*N_];
__device__ float g_ab[B_*N_];
__device__ float g_dg[B_*N_];
__device__ float g_wt[B_*N_];
__device__ float g_sumw[B_];
__device__ float g_c1[B_*N_];
__device__ float g_c2[B_*N_];
__device__ float g_Z[B_*NH_*N_];
__device__ float g_w1[B_*NH_*N_];
__device__ float g_w2[B_*NH_*N_];
__device__ float g_r1[B_*NH_*N_];
__device__ float g_r2[B_*NH_*N_];
__device__ float g_A1[B_*H_];
__device__ float g_A2[B_*H_];
__device__ float g_pm[B_*H_];

__device__ __forceinline__ bool d_pred(const int* P, int i){ return P[i]==1; }
__device__ __forceinline__ bool d_single(const int* P, int i){ return (i==0) || (i>=2 && P[i-2]==1); }

// ---------------- init: zero atomically-accumulated buffers ----------------
__global__ void k_init(){
  int i = blockIdx.x*blockDim.x + threadIdx.x;
  if (i < B_*N_) g_vg2[i] = 0.f;
  if (i < B_*H_){ g_A1[i]=0.f; g_A2[i]=0.f; }
}

// ---------------- var_in (rolled neighbor average) ----------------
__global__ void k_varin(const float* __restrict__ x, const int* __restrict__ pp){
  int idx = blockIdx.x*blockDim.x + threadIdx.x;
  if (idx >= B_*N_*H_) return;
  int hh = idx % H_;
  int n  = (idx / H_) % N_;
  int b  = idx / (N_*H_);
  bool single = (n==0) || (n>=2 && pp[b*N_+n-2]==1);
  int np = (n+1)&(N_-1);
  int nm = (n+N_-1)&(N_-1);
  float xn = x[((size_t)b*N_+np)*H_+hh];
  float v = single ? xn : 0.5f*(x[((size_t)b*N_+nm)*H_+hh] + xn);
  g_var_in[idx] = v;
}

// ---------------- tf32 tensor-core GEMM: C = alpha*(A @ W^T + bias) ----------------
// A: [8192,768] row-major; W: [768,768] row-major ([n][k]); 128x128 block tile,
// k-tile 32, 8 warps as 2(m)x4(n), warp tile 64x32 (4x2 wmma 16x16x8 frags).
#define PADK 40
#define PADC 72
__global__ __launch_bounds__(256) void k_gemm_tc(const float* __restrict__ A,
                                                 const float* __restrict__ W,
                                                 const float* __restrict__ bias,
                                                 float* __restrict__ C, float alpha){
  __shared__ float sm[2*128*PADK];          // 40960 B; Cs (128*72=9216 floats) aliases
  float* As = sm;
  float* Bs = sm + 128*PADK;
  float* Cs = sm;
  int tid = threadIdx.x;
  int m0 = blockIdx.y*128, n0 = blockIdx.x*128;
  int wid = tid>>5, wm = wid>>2, wn = wid&3;
  wmma::fragment<wmma::accumulator,16,16,8,float> acc[4][2];
  #pragma unroll
  for(int i=0;i<4;i++)
    #pragma unroll
    for(int j=0;j<2;j++) wmma::fill_fragment(acc[i][j], 0.f);
  for (int k0=0;k0<H_;k0+=32){
    __syncthreads();
    #pragma unroll
    for (int it=0; it<4; it++){
      int lin = tid + it*256;
      int r = lin>>3, q = lin&7;
      *(float4*)(As + r*PADK + q*4) = *(const float4*)(A + (size_t)(m0+r)*H_ + k0 + q*4);
      *(float4*)(Bs + r*PADK + q*4) = *(const float4*)(W + (size_t)(n0+r)*H_ + k0 + q*4);
    }
    __syncthreads();
    #pragma unroll
    for (int ks=0; ks<4; ks++){
      wmma::fragment<wmma::matrix_a,16,16,8,wmma::precision::tf32,wmma::row_major> af[4];
      wmma::fragment<wmma::matrix_b,16,16,8,wmma::precision::tf32,wmma::col_major> bf[2];
      #pragma unroll
      for(int i=0;i<4;i++){
        wmma::load_matrix_sync(af[i], As + (wm*64+i*16)*PADK + ks*8, PADK);
        #pragma unroll
        for(int t=0;t<af[i].num_elements;t++) af[i].x[t] = wmma::__float_to_tf32(af[i].x[t]);
      }
      #pragma unroll
      for(int j=0;j<2;j++){
        wmma::load_matrix_sync(bf[j], Bs + (wn*32+j*16)*PADK + ks*8, PADK);
        #pragma unroll
        for(int t=0;t<bf[j].num_elements;t++) bf[j].x[t] = wmma::__float_to_tf32(bf[j].x[t]);
      }
      #pragma unroll
      for(int i=0;i<4;i++)
        #pragma unroll
        for(int j=0;j<2;j++) wmma::mma_sync(acc[i][j], af[i], bf[j], acc[i][j]);
    }
  }
  #pragma unroll
  for (int c=0;c<2;c++){
    __syncthreads();
    if ((wn>>1)==c){
      #pragma unroll
      for(int i=0;i<4;i++)
        #pragma unroll
        for(int j=0;j<2;j++)
          wmma::store_matrix_sync(Cs + (wm*64+i*16)*PADC + (wn&1)*32 + j*16, acc[i][j], PADC, wmma::mem_row_major);
    }
    __syncthreads();
    #pragma unroll
    for (int it=0; it<8; it++){
      int lin = tid + it*256;
      int r = lin>>4, q = lin&15;
      int n = n0 + c*64 + q*4;
      float4 cv = *(float4*)(Cs + r*PADC + q*4);
      float4 bv = *(const float4*)(bias + n);
      float4 o;
      o.x = alpha*(cv.x+bv.x); o.y = alpha*(cv.y+bv.y);
      o.z = alpha*(cv.z+bv.z); o.w = alpha*(cv.w+bv.w);
      *(float4*)(C + (size_t)(m0+r)*H_ + n) = o;
    }
  }
}

// ---------------- edge score ----------------
__global__ __launch_bounds__(256) void k_score(const float* __restrict__ Wsc, const float* __restrict__ bsc){
  int row = blockIdx.x;
  size_t base = (size_t)row * H_;
  float p = 0.f;
  for (int h = threadIdx.x; h < H_; h += 256)
    p += tanhf(g_varfeat[base+h])*Wsc[h] + tanhf(g_symfeat[base+h])*Wsc[H_+h];
  for (int o=16;o;o>>=1) p += __shfl_xor_sync(0xffffffffu, p, o);
  __shared__ float red[8];
  if ((threadIdx.x&31)==0) red[threadIdx.x>>5] = p;
  __syncthreads();
  if (threadIdx.x==0){
    float t = bsc[0];
    #pragma unroll
    for (int i=0;i<8;i++) t += red[i];
    g_sc[row] = t >= 0.f ? t : 0.02f*t;
  }
}

// ---------------- cross scores -> VG^2 diagonal ----------------
__global__ __launch_bounds__(128) void k_cross(const float* __restrict__ x, const float* __restrict__ Wc,
                                               const float* __restrict__ bc, const int* __restrict__ occ){
  int pid = blockIdx.x;
  int b = pid / M_;
  int o0 = occ[pid*2], o1 = occ[pid*2+1];
  const float* x0 = x + ((size_t)b*N_+o0)*H_;
  const float* x1 = x + ((size_t)b*N_+o1)*H_;
  float p = 0.f;
  for (int h=threadIdx.x; h<H_; h+=128) p += 0.5f*(x0[h]+x1[h])*Wc[h];
  for (int o=16;o;o>>=1) p += __shfl_xor_sync(0xffffffffu, p, o);
  __shared__ float red[4];
  if ((threadIdx.x&31)==0) red[threadIdx.x>>5] = p;
  __syncthreads();
  if (threadIdx.x==0){
    float t = bc[0] + red[0]+red[1]+red[2]+red[3];
    t = t >= 0.f ? t : 0.02f*t;
    atomicAdd(&g_vg2[b*N_+o0], t*t);
    atomicAdd(&g_vg2[b*N_+o1], t*t);
  }
}

// ---------------- AG band + node weights ----------------
__global__ void k_band(const int* __restrict__ pp){
  int idx = blockIdx.x*blockDim.x + threadIdx.x;
  if (idx >= B_*N_) return;
  int b = idx >> 10, n = idx & (N_-1);
  const int* P = pp + b*N_;
  const float* s = g_sc + b*N_;
  float a = 0.f;
  if (n < N_-1){
    float sl1 = d_pred(P,n+1) ? s[n+1] : 0.f;
    bool up0 = d_pred(P,n) && (n<=1 || !d_single(P,n));
    float su0 = up0 ? s[n] : 0.f;
    a = sl1 + su0;
  }
  g_ab[idx] = a;
  bool up = d_pred(P,n) && (n<=1 || !d_single(P,n));
  bool tr = up && (n>=1);
  g_wt[idx] = d_pred(P,n) ? (tr?3.f:2.f) : 0.f;
}

__global__ __launch_bounds__(1024) void k_sumw(){
  int b = blockIdx.x;
  float v = g_wt[b*N_ + threadIdx.x];
  for (int o=16;o;o>>=1) v += __shfl_xor_sync(0xffffffffu, v, o);
  __shared__ float red[32];
  if ((threadIdx.x&31)==0) red[threadIdx.x>>5] = v;
  __syncthreads();
  if (threadIdx.x < 32){
    float t = red[threadIdx.x];
    for (int o=16;o;o>>=1) t += __shfl_xor_sync(0xffffffffu, t, o);
    if (threadIdx.x==0) g_sumw[b] = t;
  }
}

__global__ void k_coef(const int* __restrict__ pp){
  int idx = blockIdx.x*blockDim.x + threadIdx.x;
  if (idx >= B_*N_) return;
  int b = idx >> 10, n = idx & (N_-1);
  const int* P = pp + b*N_;
  float am1 = (n>=1) ? g_ab[b*N_+n-1] : 0.f;
  float an = g_ab[idx];
  g_dg[idx] = 0.8f*(am1*am1 + an*an) + g_vg2[idx];
  float sw = g_sumw[b];
  int nm = (n+N_-1)&(N_-1), np = (n+1)&(N_-1);
  float c1 = g_wt[b*N_+nm]*(d_single(P,nm)?1.f:0.5f)
           + g_wt[b*N_+np]*(d_single(P,np)?0.f:0.5f);
  g_c1[idx] = c1 / sw;
  g_c2[idx] = g_wt[idx] / sw;
}

// ---------------- attention pass 1: Z[bh][n] = sum_m exp(S[n,m]+bias) ----------------
// grid (96, 8): block = 128 Q rows x all 1024 K rows, tf32 wmma, fused epilogue.
__global__ __launch_bounds__(256) void k_attn1(){
  extern __shared__ float sm[];
  float* Qs = sm;                 // 128*72
  float* Ks = sm + 128*PADC;      // 128*72 ; Cs aliases Ks
  float* Cs = Ks;
  int tid = threadIdx.x;
  int bh = blockIdx.x, b = bh/NH_, h = bh - b*NH_;
  int n0 = blockIdx.y*128;
  int wid = tid>>5, wm = wid>>2, wn = wid&3;
  const float* Q = g_Qb + (size_t)b*N_*H_ + h*64;
  const float* K = g_Kb + (size_t)b*N_*H_ + h*64;
  // load Q tile (resident)
  #pragma unroll
  for (int it=0; it<8; it++){
    int lin = tid + it*256;
    int r = lin>>4, q = lin&15;
    *(float4*)(Qs + r*PADC + q*4) = *(const float4*)(Q + (size_t)(n0+r)*H_ + q*4);
  }
  // per-thread row params
  int row = tid>>1;
  int n = n0 + row;
  const float* ab = g_ab + b*N_;
  float dgv = g_dg[b*N_+n];
  float anm2 = (n>=2)? ab[n-2] : 0.f;
  float anm1 = (n>=1)? ab[n-1] : 0.f;
  float an   = ab[n];
  float anp1 = (n<N_-1)? ab[n+1] : 0.f;
  float t1 = 0.2f*an, tm1 = 0.2f*anm1, t2 = 0.8f*an*anp1, tm2 = 0.8f*anm2*anm1;
  float Zpart = 0.f;
  int half = tid&1;
  for (int mt=0; mt<8; mt++){
    __syncthreads();
    #pragma unroll
    for (int it=0; it<8; it++){
      int lin = tid + it*256;
      int r = lin>>4, q = lin&15;
      *(float4*)(Ks + r*PADC + q*4) = *(const float4*)(K + (size_t)(mt*128+r)*H_ + q*4);
    }
    __syncthreads();
    wmma::fragment<wmma::accumulator,16,16,8,float> acc[4][2];
    #pragma unroll
    for(int i=0;i<4;i++)
      #pragma unroll
      for(int j=0;j<2;j++) wmma::fill_fragment(acc[i][j], 0.f);
    #pragma unroll
    for (int ks=0; ks<8; ks++){
      wmma::fragment<wmma::matrix_a,16,16,8,wmma::precision::tf32,wmma::row_major> af[4];
      wmma::fragment<wmma::matrix_b,16,16,8,wmma::precision::tf32,wmma::col_major> bf[2];
      #pragma unroll
      for(int i=0;i<4;i++){
        wmma::load_matrix_sync(af[i], Qs + (wm*64+i*16)*PADC + ks*8, PADC);
        #pragma unroll
        for(int t=0;t<af[i].num_elements;t++) af[i].x[t] = wmma::__float_to_tf32(af[i].x[t]);
      }
      #pragma unroll
      for(int j=0;j<2;j++){
        wmma::load_matrix_sync(bf[j], Ks + (wn*32+j*16)*PADC + ks*8, PADC);
        #pragma unroll
        for(int t=0;t<bf[j].num_elements;t++) bf[j].x[t] = wmma::__float_to_tf32(bf[j].x[t]);
      }
      #pragma unroll
      for(int i=0;i<4;i++)
        #pragma unroll
        for(int j=0;j<2;j++) wmma::mma_sync(acc[i][j], af[i], bf[j], acc[i][j]);
    }
    #pragma unroll
    for (int c=0;c<2;c++){
      __syncthreads();
      if ((wn>>1)==c){
        #pragma unroll
        for(int i=0;i<4;i++)
          #pragma unroll
          for(int j=0;j<2;j++)
            wmma::store_matrix_sync(Cs + (wm*64+i*16)*PADC + (wn&1)*32 + j*16, acc[i][j], PADC, wmma::mem_row_major);
      }
      __syncthreads();
      float s = 0.f;
      #pragma unroll
      for (int j=0;j<32;j++){
        int lc = half*32 + j;
        int m = mt*128 + c*64 + lc;
        float xv = Cs[row*PADC + lc];
        int d = m - n;
        float bias = (d==0)?dgv : (d==1)?t1 : (d==-1)?tm1 : (d==2)?t2 : (d==-2)?tm2 : 0.f;
        s += __expf(xv + bias);
      }
      s += __shfl_xor_sync(0xffffffffu, s, 1);
      Zpart += s;
    }
  }
  if (half==0) g_Z[(size_t)bh*N_ + n] = Zpart;
}

// ---------------- per-row weights w = c / Z ----------------
__global__ void k_w(){
  int idx = blockIdx.x*blockDim.x + threadIdx.x;
  if (idx >= B_*NH_*N_) return;
  int n = idx & (N_-1);
  int bh = idx >> 10;
  int b = bh / NH_;
  float iz = 1.f / g_Z[idx];
  g_w1[idx] = g_c1[b*N_+n] * iz;
  g_w2[idx] = g_c2[b*N_+n] * iz;
}

// ---------------- attention pass 2: r[m] = sum_n w[n]*exp(S[n,m]+bias) ----------------
// grid (96, 8): block = 128 K rows (m) x all 1024 Q rows (n), C[m][n] = K·Q^T.
__global__ __launch_bounds__(256) void k_attn2(){
  extern __shared__ float sm[];
  float* As = sm;                 // K rows tile, resident
  float* Bs = sm + 128*PADC;      // Q tile streamed; Cs aliases
  float* Cs = Bs;
  __shared__ float colp[7*64];
  int tid = threadIdx.x;
  int bh = blockIdx.x, b = bh/NH_, h = bh - b*NH_;
  int m0 = blockIdx.y*128;
  int wid = tid>>5, wm = wid>>2, wn = wid&3;
  const float* Q = g_Qb + (size_t)b*N_*H_ + h*64;
  const float* K = g_Kb + (size_t)b*N_*H_ + h*64;
  #pragma unroll
  for (int it=0; it<8; it++){
    int lin = tid + it*256;
    int r = lin>>4, q = lin&15;
    *(float4*)(As + r*PADC + q*4) = *(const float4*)(K + (size_t)(m0+r)*H_ + q*4);
  }
  int row = tid>>1;
  int half = tid&1;
  int mg = m0 + row;
  const float* ab = g_ab + b*N_;
  float R1 = 0.f, R2 = 0.f;
  for (int nt=0; nt<8; nt++){
    __syncthreads();
    #pragma unroll
    for (int it=0; it<8; it++){
      int lin = tid + it*256;
      int r = lin>>4, q = lin&15;
      *(float4*)(Bs + r*PADC + q*4) = *(const float4*)(Q + (size_t)(nt*128+r)*H_ + q*4);
    }
    __syncthreads();
    wmma::fragment<wmma::accumulator,16,16,8,float> acc[4][2];
    #pragma unroll
    for(int i=0;i<4;i++)
      #pragma unroll
      for(int j=0;j<2;j++) wmma::fill_fragment(acc[i][j], 0.f);
    #pragma unroll
    for (int ks=0; ks<8; ks++){
      wmma::fragment<wmma::matrix_a,16,16,8,wmma::precision::tf32,wmma::row_major> af[4];
      wmma::fragment<wmma::matrix_b,16,16,8,wmma::precision::tf32,wmma::col_major> bf[2];
      #pragma unroll
      for(int i=0;i<4;i++){
        wmma::load_matrix_sync(af[i], As + (wm*64+i*16)*PADC + ks*8, PADC);
        #pragma unroll
        for(int t=0;t<af[i].num_elements;t++) af[i].x[t] = wmma::__float_to_tf32(af[i].x[t]);
      }
      #pragma unroll
      for(int j=0;j<2;j++){
        wmma::load_matrix_sync(bf[j], Bs + (wn*32+j*16)*PADC + ks*8, PADC);
        #pragma unroll
        for(int t=0;t<bf[j].num_elements;t++) bf[j].x[t] = wmma::__float_to_tf32(bf[j].x[t]);
      }
      #pragma unroll
      for(int i=0;i<4;i++)
        #pragma unroll
        for(int j=0;j<2;j++) wmma::mma_sync(acc[i][j], af[i], bf[j], acc[i][j]);
    }
    #pragma unroll
    for (int c=0;c<2;c++){
      __syncthreads();
      if ((wn>>1)==c){
        #pragma unroll
        for(int i=0;i<4;i++)
          #pragma unroll
          for(int j=0;j<2;j++)
            wmma::store_matrix_sync(Cs + (wm*64+i*16)*PADC + (wn&1)*32 + j*16, acc[i][j], PADC, wmma::mem_row_major);
      }
      if (tid < 64){
        int n = nt*128 + c*64 + tid;
        float anm2 = (n>=2)? ab[n-2] : 0.f;
        float anm1 = (n>=1)? ab[n-1] : 0.f;
        float an   = ab[n];
        float anp1 = (n<N_-1)? ab[n+1] : 0.f;
        colp[0*64+tid] = g_dg[b*N_+n];
        colp[1*64+tid] = 0.2f*an;
        colp[2*64+tid] = 0.2f*anm1;
        colp[3*64+tid] = 0.8f*an*anp1;
        colp[4*64+tid] = 0.8f*anm2*anm1;
        colp[5*64+tid] = g_w1[(size_t)bh*N_+n];
        colp[6*64+tid] = g_w2[(size_t)bh*N_+n];
      }
      __syncthreads();
      float r1 = 0.f, r2 = 0.f;
      #pragma unroll
      for (int j=0;j<32;j++){
        int lc = half*32 + j;
        int n = nt*128 + c*64 + lc;
        float xv = Cs[row*PADC + lc];
        int d = mg - n;
        float bias = (d==0)?colp[0*64+lc] : (d==1)?colp[1*64+lc] : (d==-1)?colp[2*64+lc]
                   : (d==2)?colp[3*64+lc] : (d==-2)?colp[4*64+lc] : 0.f;
        float P = __expf(xv + bias);
        r1 += colp[5*64+lc]*P;
        r2 += colp[6*64+lc]*P;
      }
      R1 += r1 + __shfl_xor_sync(0xffffffffu, r1, 1);
      R2 += r2 + __shfl_xor_sync(0xffffffffu, r2, 1);
    }
  }
  if (half==0){
    g_r1[(size_t)bh*N_ + mg] = R1;
    g_r2[(size_t)bh*N_ + mg] = R2;
  }
}

// ---------------- A = r @ V (per batch, concat heads) ----------------
__global__ __launch_bounds__(768) void k_matvec(){
  int b = blockIdx.x, f = threadIdx.x, h = f >> 6;
  int m0 = blockIdx.y*64;
  const float* r1 = g_r1 + ((size_t)b*NH_+h)*N_;
  const float* r2 = g_r2 + ((size_t)b*NH_+h)*N_;
  float a1=0.f, a2=0.f;
  for (int m=m0; m<m0+64; m++){
    float vv = g_Vb[((size_t)b*N_+m)*H_+f];
    a1 += r1[m]*vv; a2 += r2[m]*vv;
  }
  atomicAdd(&g_A1[b*H_+f], a1);
  atomicAdd(&g_A2[b*H_+f], a2);
}

// ---------------- final projections + broadcast ----------------
__global__ __launch_bounds__(768) void k_final(const float* __restrict__ Wo, const float* __restrict__ bo,
                                               const float* __restrict__ Wa, const float* __restrict__ ba){
  int b = blockIdx.x, o = threadIdx.x;
  __shared__ float u1s[H_], u2s[H_];
  const float* w = Wo + (size_t)o*H_;
  const float* A1 = g_A1 + b*H_;
  const float* A2 = g_A2 + b*H_;
  float u1 = bo[o], u2 = bo[o];
  for (int i=0;i<H_;i++){ u1 += w[i]*A1[i]; u2 += w[i]*A2[i]; }
  u1s[o] = u1; u2s[o] = u2;
  __syncthreads();
  const float* wa = Wa + (size_t)o*2*H_;
  float p = ba[o];
  for (int i=0;i<H_;i++) p += wa[i]*u1s[i] + wa[H_+i]*u2s[i];
  g_pm[b*H_+o] = p;
}

__global__ void k_bcast(float* __restrict__ out){
  int idx = blockIdx.x*blockDim.x + threadIdx.x;
  if (idx >= B_*N_*H_) return;
  int f = idx % H_;
  int b = idx / (N_*H_);
  out[idx] = g_pm[b*H_+f];
}

// ---------------- launch ----------------
extern "C" void kernel_launch(void* const* d_in, const int* in_sizes, int n_in,
                              void* d_out, int out_size){
  (void)in_sizes; (void)n_in; (void)out_size;
  const float* x      = (const float*)d_in[0];
  const float* W_var  = (const float*)d_in[3];
  const float* b_var  = (const float*)d_in[4];
  const float* W_sym  = (const float*)d_in[5];
  const float* b_sym  = (const float*)d_in[6];
  const float* W_sc   = (const float*)d_in[7];
  const float* b_scb  = (const float*)d_in[8];
  const float* W_cr   = (const float*)d_in[9];
  const float* b_cr   = (const float*)d_in[10];
  const float* W_atom = (const float*)d_in[11];
  const float* b_atom = (const float*)d_in[12];
  const float* W_q    = (const float*)d_in[13];
  const float* b_q    = (const float*)d_in[14];
  const float* W_k    = (const float*)d_in[15];
  const float* b_k    = (const float*)d_in[16];
  const float* W_v    = (const float*)d_in[17];
  const float* b_v    = (const float*)d_in[18];
  const float* W_o    = (const float*)d_in[19];
  const float* b_o    = (const float*)d_in[20];
  const int*   pp     = (const int*)d_in[21];
  const int*   occ    = (const int*)d_in[24];
  float* out = (float*)d_out;

  float *p_varin, *p_varfeat, *p_symfeat, *p_Q, *p_K, *p_V;
  cudaGetSymbolAddress((void**)&p_varin,   g_var_in);
  cudaGetSymbolAddress((void**)&p_varfeat, g_varfeat);
  cudaGetSymbolAddress((void**)&p_symfeat, g_symfeat);
  cudaGetSymbolAddress((void**)&p_Q,       g_Qb);
  cudaGetSymbolAddress((void**)&p_K,       g_Kb);
  cudaGetSymbolAddress((void**)&p_V,       g_Vb);

  static bool attr_done = false;
  if (!attr_done){
    cudaFuncSetAttribute(k_attn1, cudaFuncAttributeMaxDynamicSharedMemorySize, 2*128*PADC*4);
    cudaFuncSetAttribute(k_attn2, cudaFuncAttributeMaxDynamicSharedMemorySize, 2*128*PADC*4);
    attr_done = true;
  }

  k_init<<<(B_*N_*H_ > B_*N_ ? (B_*N_+255)/256 : 1)*1 + 0, 256>>>();
  k_varin<<<(B_*N_*H_+255)/256, 256>>>(x, pp);

  dim3 gp(H_/128, (B_*N_)/128);
  k_gemm_tc<<<gp,256>>>(p_varin, W_var, b_var, p_varfeat, 1.f);
  k_gemm_tc<<<gp,256>>>(x,       W_sym, b_sym, p_symfeat, 1.f);
  k_gemm_tc<<<gp,256>>>(x,       W_q,   b_q,   p_Q, 0.125f);
  k_gemm_tc<<<gp,256>>>(x,       W_k,   b_k,   p_K, 1.f);
  k_gemm_tc<<<gp,256>>>(x,       W_v,   b_v,   p_V, 1.f);

  k_score<<<B_*N_, 256>>>(W_sc, b_scb);
  k_cross<<<B_*M_, 128>>>(x, W_cr, b_cr, occ);
  k_band<<<(B_*N_+255)/256, 256>>>(pp);
  k_sumw<<<B_, 1024>>>();
  k_coef<<<(B_*N_+255)/256, 256>>>(pp);

  dim3 ga(B_*NH_, N_/128);
  k_attn1<<<ga, 256, 2*128*PADC*4>>>();
  k_w<<<(B_*NH_*N_+255)/256, 256>>>();
  k_attn2<<<ga, 256, 2*128*PADC*4>>>();

  dim3 gmv(B_, 16);
  k_matvec<<<gmv, 768>>>();
  k_final<<<B_, 768>>>(W_o, b_o, W_atom, b_atom);
  k_bcast<<<(B_*N_*H_+255)/256, 256>>>(out);
}

// round 3
// speedup vs baseline: 1.4131x; 1.0392x over previous
#include <cuda_runtime.h>
#include <mma.h>
using namespace nvcuda;

#define B_ 8
#define N_ 1024
#define H_ 768
#define NH_ 12
#define M_ 256

// ---------------- scratch (device globals; no allocation) ----------------
__device__ float g_Qb[B_*N_*H_];
__device__ float g_Kb[B_*N_*H_];
__device__ float g_Vb[B_*N_*H_];
__device__ float g_sc[B_*N_];          // raw score accumulator (pre-lrelu)
__device__ float g_vg2[B_*N_];
__device__ float g_ab[B_*N_];
__device__ float g_dg[B_*N_];
__device__ float g_wt[B_*N_];
__device__ float g_sumw[B_];
__device__ float g_c1[B_*N_];
__device__ float g_c2[B_*N_];
__device__ float g_Z[B_*NH_*N_];
__device__ float g_w1[B_*NH_*N_];
__device__ float g_w2[B_*NH_*N_];
__device__ float g_r1[B_*NH_*N_];
__device__ float g_r2[B_*NH_*N_];
__device__ float g_A1[B_*H_];
__device__ float g_A2[B_*H_];
__device__ float g_pm[B_*H_];

__device__ __forceinline__ bool d_pred(const int* P, int i){ return P[i]==1; }
__device__ __forceinline__ bool d_single(const int* P, int i){ return (i==0) || (i>=2 && P[i-2]==1); }
__device__ __forceinline__ float d_lrelu(float t){ return t >= 0.f ? t : 0.02f*t; }

// ---------------- init: zero accumulators; g_sc = score bias ----------------
__global__ void k_init(const float* __restrict__ bsc){
  int i = blockIdx.x*blockDim.x + threadIdx.x;
  if (i < B_*N_){ g_vg2[i] = 0.f; g_sc[i] = bsc[0]; }
  if (i < B_*H_){ g_A1[i]=0.f; g_A2[i]=0.f; }
}

// ---------------- tf32 tensor-core GEMM, fused variants ----------------
// C = alpha*(A' @ W^T + bias)    (A' = A, or rolled-neighbor average of x if AVG)
// SCORE: instead of writing C, accumulate  g_sc[row] += sum_col tanh(acc+bias)*Wsc[off+col]
#define PADK 40
#define PADC 72
template<bool AVG, bool SCORE>
__global__ __launch_bounds__(256,2) void k_gemm_tc(const float* __restrict__ A,
                                                   const float* __restrict__ W,
                                                   const float* __restrict__ bias,
                                                   float* __restrict__ C, float alpha,
                                                   const float* __restrict__ Wsc, int wsc_off,
                                                   const int* __restrict__ pp){
  __shared__ float sm[2*128*PADK];          // As | Bs ; Cs aliases (128*PADC <= 2*128*PADK)
  float* As = sm;
  float* Bs = sm + 128*PADK;
  float* Cs = sm;
  int tid = threadIdx.x;
  int m0 = blockIdx.y*128, n0 = blockIdx.x*128;
  int wid = tid>>5, wm = wid>>2, wn = wid&3;
  wmma::fragment<wmma::accumulator,16,16,8,float> acc[4][2];
  #pragma unroll
  for(int i=0;i<4;i++)
    #pragma unroll
    for(int j=0;j<2;j++) wmma::fill_fragment(acc[i][j], 0.f);
  for (int k0=0;k0<H_;k0+=32){
    __syncthreads();
    #pragma unroll
    for (int it=0; it<4; it++){
      int lin = tid + it*256;
      int r = lin>>3, q = lin&7;
      float4 av;
      if (AVG){
        int m = m0 + r;
        int b = m >> 10, n = m & (N_-1);
        bool single = (n==0) || (n>=2 && pp[b*N_+n-2]==1);
        int np = (n+1)&(N_-1), nm = (n+N_-1)&(N_-1);
        float4 xn = *(const float4*)(A + ((size_t)(b<<10)+np)*H_ + k0 + q*4);
        if (single) av = xn;
        else {
          float4 xp = *(const float4*)(A + ((size_t)(b<<10)+nm)*H_ + k0 + q*4);
          av.x = 0.5f*(xp.x+xn.x); av.y = 0.5f*(xp.y+xn.y);
          av.z = 0.5f*(xp.z+xn.z); av.w = 0.5f*(xp.w+xn.w);
        }
      } else {
        av = *(const float4*)(A + (size_t)(m0+r)*H_ + k0 + q*4);
      }
      float4 bv = *(const float4*)(W + (size_t)(n0+r)*H_ + k0 + q*4);
      float* ad = As + r*PADK + q*4;
      ad[0]=wmma::__float_to_tf32(av.x); ad[1]=wmma::__float_to_tf32(av.y);
      ad[2]=wmma::__float_to_tf32(av.z); ad[3]=wmma::__float_to_tf32(av.w);
      float* bd = Bs + r*PADK + q*4;
      bd[0]=wmma::__float_to_tf32(bv.x); bd[1]=wmma::__float_to_tf32(bv.y);
      bd[2]=wmma::__float_to_tf32(bv.z); bd[3]=wmma::__float_to_tf32(bv.w);
    }
    __syncthreads();
    #pragma unroll
    for (int ks=0; ks<4; ks++){
      wmma::fragment<wmma::matrix_a,16,16,8,wmma::precision::tf32,wmma::row_major> af[4];
      wmma::fragment<wmma::matrix_b,16,16,8,wmma::precision::tf32,wmma::col_major> bf[2];
      #pragma unroll
      for(int i=0;i<4;i++) wmma::load_matrix_sync(af[i], As + (wm*64+i*16)*PADK + ks*8, PADK);
      #pragma unroll
      for(int j=0;j<2;j++) wmma::load_matrix_sync(bf[j], Bs + (wn*32+j*16)*PADK + ks*8, PADK);
      #pragma unroll
      for(int i=0;i<4;i++)
        #pragma unroll
        for(int j=0;j<2;j++) wmma::mma_sync(acc[i][j], af[i], bf[j], acc[i][j]);
    }
  }
  if (SCORE){
    int row = tid>>1, half = tid&1;
    float p = 0.f;
    #pragma unroll
    for (int c=0;c<2;c++){
      __syncthreads();
      if ((wn>>1)==c){
        #pragma unroll
        for(int i=0;i<4;i++)
          #pragma unroll
          for(int j=0;j<2;j++)
            wmma::store_matrix_sync(Cs + (wm*64+i*16)*PADC + (wn&1)*32 + j*16, acc[i][j], PADC, wmma::mem_row_major);
      }
      __syncthreads();
      #pragma unroll
      for (int j=0;j<32;j++){
        int lc = half*32 + j;
        int col = n0 + c*64 + lc;
        float v = Cs[row*PADC + lc] + bias[col];
        p += tanhf(v)*Wsc[wsc_off + col];
      }
    }
    p += __shfl_xor_sync(0xffffffffu, p, 1);
    if (half==0) atomicAdd(&g_sc[m0+row], p);
  } else {
    #pragma unroll
    for (int c=0;c<2;c++){
      __syncthreads();
      if ((wn>>1)==c){
        #pragma unroll
        for(int i=0;i<4;i++)
          #pragma unroll
          for(int j=0;j<2;j++)
            wmma::store_matrix_sync(Cs + (wm*64+i*16)*PADC + (wn&1)*32 + j*16, acc[i][j], PADC, wmma::mem_row_major);
      }
      __syncthreads();
      #pragma unroll
      for (int it=0; it<8; it++){
        int lin = tid + it*256;
        int r = lin>>4, q = lin&15;
        int n = n0 + c*64 + q*4;
        float4 cv = *(float4*)(Cs + r*PADC + q*4);
        float4 bv = *(const float4*)(bias + n);
        float4 o;
        o.x = alpha*(cv.x+bv.x); o.y = alpha*(cv.y+bv.y);
        o.z = alpha*(cv.z+bv.z); o.w = alpha*(cv.w+bv.w);
        *(float4*)(C + (size_t)(m0+r)*H_ + n) = o;
      }
    }
  }
}

// ---------------- cross scores -> VG^2 diagonal ----------------
__global__ __launch_bounds__(128) void k_cross(const float* __restrict__ x, const float* __restrict__ Wc,
                                               const float* __restrict__ bc, const int* __restrict__ occ){
  int pid = blockIdx.x;
  int b = pid / M_;
  int o0 = occ[pid*2], o1 = occ[pid*2+1];
  const float* x0 = x + ((size_t)b*N_+o0)*H_;
  const float* x1 = x + ((size_t)b*N_+o1)*H_;
  float p = 0.f;
  for (int h=threadIdx.x; h<H_; h+=128) p += 0.5f*(x0[h]+x1[h])*Wc[h];
  for (int o=16;o;o>>=1) p += __shfl_xor_sync(0xffffffffu, p, o);
  __shared__ float red[4];
  if ((threadIdx.x&31)==0) red[threadIdx.x>>5] = p;
  __syncthreads();
  if (threadIdx.x==0){
    float t = d_lrelu(bc[0] + red[0]+red[1]+red[2]+red[3]);
    atomicAdd(&g_vg2[b*N_+o0], t*t);
    atomicAdd(&g_vg2[b*N_+o1], t*t);
  }
}

// ---------------- AG band + node weights (lrelu applied here) ----------------
__global__ void k_band(const int* __restrict__ pp){
  int idx = blockIdx.x*blockDim.x + threadIdx.x;
  if (idx >= B_*N_) return;
  int b = idx >> 10, n = idx & (N_-1);
  const int* P = pp + b*N_;
  const float* s = g_sc + b*N_;
  float a = 0.f;
  if (n < N_-1){
    float sl1 = d_pred(P,n+1) ? d_lrelu(s[n+1]) : 0.f;
    bool up0 = d_pred(P,n) && (n<=1 || !d_single(P,n));
    float su0 = up0 ? d_lrelu(s[n]) : 0.f;
    a = sl1 + su0;
  }
  g_ab[idx] = a;
  bool up = d_pred(P,n) && (n<=1 || !d_single(P,n));
  bool tr = up && (n>=1);
  g_wt[idx] = d_pred(P,n) ? (tr?3.f:2.f) : 0.f;
}

__global__ __launch_bounds__(1024) void k_sumw(){
  int b = blockIdx.x;
  float v = g_wt[b*N_ + threadIdx.x];
  for (int o=16;o;o>>=1) v += __shfl_xor_sync(0xffffffffu, v, o);
  __shared__ float red[32];
  if ((threadIdx.x&31)==0) red[threadIdx.x>>5] = v;
  __syncthreads();
  if (threadIdx.x < 32){
    float t = red[threadIdx.x];
    for (int o=16;o;o>>=1) t += __shfl_xor_sync(0xffffffffu, t, o);
    if (threadIdx.x==0) g_sumw[b] = t;
  }
}

__global__ void k_coef(const int* __restrict__ pp){
  int idx = blockIdx.x*blockDim.x + threadIdx.x;
  if (idx >= B_*N_) return;
  int b = idx >> 10, n = idx & (N_-1);
  const int* P = pp + b*N_;
  float am1 = (n>=1) ? g_ab[b*N_+n-1] : 0.f;
  float an = g_ab[idx];
  g_dg[idx] = 0.8f*(am1*am1 + an*an) + g_vg2[idx];
  float sw = g_sumw[b];
  int nm = (n+N_-1)&(N_-1), np = (n+1)&(N_-1);
  float c1 = g_wt[b*N_+nm]*(d_single(P,nm)?1.f:0.5f)
           + g_wt[b*N_+np]*(d_single(P,np)?0.f:0.5f);
  g_c1[idx] = c1 / sw;
  g_c2[idx] = g_wt[idx] / sw;
}

// ---------------- attention pass 1: Z[bh][n] = sum_m exp(S[n,m]+bias) ----------------
__global__ __launch_bounds__(256,2) void k_attn1(){
  extern __shared__ float sm[];
  float* Qs = sm;                 // 128*PADC
  float* Ks = sm + 128*PADC;      // 128*PADC ; Cs aliases Ks
  float* Cs = Ks;
  int tid = threadIdx.x;
  int bh = blockIdx.x, b = bh/NH_, h = bh - b*NH_;
  int n0 = blockIdx.y*128;
  int wid = tid>>5, wm = wid>>2, wn = wid&3;
  const float* Q = g_Qb + (size_t)b*N_*H_ + h*64;
  const float* K = g_Kb + (size_t)b*N_*H_ + h*64;
  #pragma unroll
  for (int it=0; it<8; it++){
    int lin = tid + it*256;
    int r = lin>>4, q = lin&15;
    float4 v = *(const float4*)(Q + (size_t)(n0+r)*H_ + q*4);
    float* d = Qs + r*PADC + q*4;
    d[0]=wmma::__float_to_tf32(v.x); d[1]=wmma::__float_to_tf32(v.y);
    d[2]=wmma::__float_to_tf32(v.z); d[3]=wmma::__float_to_tf32(v.w);
  }
  int row = tid>>1;
  int n = n0 + row;
  const float* ab = g_ab + b*N_;
  float dgv = g_dg[b*N_+n];
  float anm2 = (n>=2)? ab[n-2] : 0.f;
  float anm1 = (n>=1)? ab[n-1] : 0.f;
  float an   = ab[n];
  float anp1 = (n<N_-1)? ab[n+1] : 0.f;
  float t1 = 0.2f*an, tm1 = 0.2f*anm1, t2 = 0.8f*an*anp1, tm2 = 0.8f*anm2*anm1;
  float Zpart = 0.f;
  int half = tid&1;
  for (int mt=0; mt<8; mt++){
    __syncthreads();
    #pragma unroll
    for (int it=0; it<8; it++){
      int lin = tid + it*256;
      int r = lin>>4, q = lin&15;
      float4 v = *(const float4*)(K + (size_t)(mt*128+r)*H_ + q*4);
      float* d = Ks + r*PADC + q*4;
      d[0]=wmma::__float_to_tf32(v.x); d[1]=wmma::__float_to_tf32(v.y);
      d[2]=wmma::__float_to_tf32(v.z); d[3]=wmma::__float_to_tf32(v.w);
    }
    __syncthreads();
    wmma::fragment<wmma::accumulator,16,16,8,float> acc[4][2];
    #pragma unroll
    for(int i=0;i<4;i++)
      #pragma unroll
      for(int j=0;j<2;j++) wmma::fill_fragment(acc[i][j], 0.f);
    #pragma unroll
    for (int ks=0; ks<8; ks++){
      wmma::fragment<wmma::matrix_a,16,16,8,wmma::precision::tf32,wmma::row_major> af[4];
      wmma::fragment<wmma::matrix_b,16,16,8,wmma::precision::tf32,wmma::col_major> bf[2];
      #pragma unroll
      for(int i=0;i<4;i++) wmma::load_matrix_sync(af[i], Qs + (wm*64+i*16)*PADC + ks*8, PADC);
      #pragma unroll
      for(int j=0;j<2;j++) wmma::load_matrix_sync(bf[j], Ks + (wn*32+j*16)*PADC + ks*8, PADC);
      #pragma unroll
      for(int i=0;i<4;i++)
        #pragma unroll
        for(int j=0;j<2;j++) wmma::mma_sync(acc[i][j], af[i], bf[j], acc[i][j]);
    }
    #pragma unroll
    for (int c=0;c<2;c++){
      __syncthreads();
      if ((wn>>1)==c){
        #pragma unroll
        for(int i=0;i<4;i++)
          #pragma unroll
          for(int j=0;j<2;j++)
            wmma::store_matrix_sync(Cs + (wm*64+i*16)*PADC + (wn&1)*32 + j*16, acc[i][j], PADC, wmma::mem_row_major);
      }
      __syncthreads();
      float s = 0.f;
      #pragma unroll
      for (int j=0;j<32;j++){
        int lc = half*32 + j;
        int m = mt*128 + c*64 + lc;
        float xv = Cs[row*PADC + lc];
        int d = m - n;
        float bias = (d==0)?dgv : (d==1)?t1 : (d==-1)?tm1 : (d==2)?t2 : (d==-2)?tm2 : 0.f;
        s += __expf(xv + bias);
      }
      s += __shfl_xor_sync(0xffffffffu, s, 1);
      Zpart += s;
    }
  }
  if (half==0) g_Z[(size_t)bh*N_ + n] = Zpart;
}

// ---------------- per-row weights w = c / Z ----------------
__global__ void k_w(){
  int idx = blockIdx.x*blockDim.x + threadIdx.x;
  if (idx >= B_*NH_*N_) return;
  int n = idx & (N_-1);
  int bh = idx >> 10;
  int b = bh / NH_;
  float iz = 1.f / g_Z[idx];
  g_w1[idx] = g_c1[b*N_+n] * iz;
  g_w2[idx] = g_c2[b*N_+n] * iz;
}

// ---------------- attention pass 2: r[m] = sum_n w[n]*exp(S[n,m]+bias) ----------------
__global__ __launch_bounds__(256,2) void k_attn2(){
  extern __shared__ float sm[];
  float* As = sm;
  float* Bs = sm + 128*PADC;
  float* Cs = Bs;
  __shared__ float colp[7*64];
  int tid = threadIdx.x;
  int bh = blockIdx.x, b = bh/NH_, h = bh - b*NH_;
  int m0 = blockIdx.y*128;
  int wid = tid>>5, wm = wid>>2, wn = wid&3;
  const float* Q = g_Qb + (size_t)b*N_*H_ + h*64;
  const float* K = g_Kb + (size_t)b*N_*H_ + h*64;
  #pragma unroll
  for (int it=0; it<8; it++){
    int lin = tid + it*256;
    int r = lin>>4, q = lin&15;
    float4 v = *(const float4*)(K + (size_t)(m0+r)*H_ + q*4);
    float* d = As + r*PADC + q*4;
    d[0]=wmma::__float_to_tf32(v.x); d[1]=wmma::__float_to_tf32(v.y);
    d[2]=wmma::__float_to_tf32(v.z); d[3]=wmma::__float_to_tf32(v.w);
  }
  int row = tid>>1;
  int half = tid&1;
  int mg = m0 + row;
  const float* ab = g_ab + b*N_;
  float R1 = 0.f, R2 = 0.f;
  for (int nt=0; nt<8; nt++){
    __syncthreads();
    #pragma unroll
    for (int it=0; it<8; it++){
      int lin = tid + it*256;
      int r = lin>>4, q = lin&15;
      float4 v = *(const float4*)(Q + (size_t)(nt*128+r)*H_ + q*4);
      float* d = Bs + r*PADC + q*4;
      d[0]=wmma::__float_to_tf32(v.x); d[1]=wmma::__float_to_tf32(v.y);
      d[2]=wmma::__float_to_tf32(v.z); d[3]=wmma::__float_to_tf32(v.w);
    }
    __syncthreads();
    wmma::fragment<wmma::accumulator,16,16,8,float> acc[4][2];
    #pragma unroll
    for(int i=0;i<4;i++)
      #pragma unroll
      for(int j=0;j<2;j++) wmma::fill_fragment(acc[i][j], 0.f);
    #pragma unroll
    for (int ks=0; ks<8; ks++){
      wmma::fragment<wmma::matrix_a,16,16,8,wmma::precision::tf32,wmma::row_major> af[4];
      wmma::fragment<wmma::matrix_b,16,16,8,wmma::precision::tf32,wmma::col_major> bf[2];
      #pragma unroll
      for(int i=0;i<4;i++) wmma::load_matrix_sync(af[i], As + (wm*64+i*16)*PADC + ks*8, PADC);
      #pragma unroll
      for(int j=0;j<2;j++) wmma::load_matrix_sync(bf[j], Bs + (wn*32+j*16)*PADC + ks*8, PADC);
      #pragma unroll
      for(int i=0;i<4;i++)
        #pragma unroll
        for(int j=0;j<2;j++) wmma::mma_sync(acc[i][j], af[i], bf[j], acc[i][j]);
    }
    #pragma unroll
    for (int c=0;c<2;c++){
      __syncthreads();
      if ((wn>>1)==c){
        #pragma unroll
        for(int i=0;i<4;i++)
          #pragma unroll
          for(int j=0;j<2;j++)
            wmma::store_matrix_sync(Cs + (wm*64+i*16)*PADC + (wn&1)*32 + j*16, acc[i][j], PADC, wmma::mem_row_major);
      }
      if (tid < 64){
        int n = nt*128 + c*64 + tid;
        float anm2 = (n>=2)? ab[n-2] : 0.f;
        float anm1 = (n>=1)? ab[n-1] : 0.f;
        float an   = ab[n];
        float anp1 = (n<N_-1)? ab[n+1] : 0.f;
        colp[0*64+tid] = g_dg[b*N_+n];
        colp[1*64+tid] = 0.2f*an;
        colp[2*64+tid] = 0.2f*anm1;
        colp[3*64+tid] = 0.8f*an*anp1;
        colp[4*64+tid] = 0.8f*anm2*anm1;
        colp[5*64+tid] = g_w1[(size_t)bh*N_+n];
        colp[6*64+tid] = g_w2[(size_t)bh*N_+n];
      }
      __syncthreads();
      float r1 = 0.f, r2 = 0.f;
      #pragma unroll
      for (int j=0;j<32;j++){
        int lc = half*32 + j;
        int n = nt*128 + c*64 + lc;
        float xv = Cs[row*PADC + lc];
        int d = mg - n;
        float bias = (d==0)?colp[0*64+lc] : (d==1)?colp[1*64+lc] : (d==-1)?colp[2*64+lc]
                   : (d==2)?colp[3*64+lc] : (d==-2)?colp[4*64+lc] : 0.f;
        float P = __expf(xv + bias);
        r1 += colp[5*64+lc]*P;
        r2 += colp[6*64+lc]*P;
      }
      R1 += r1 + __shfl_xor_sync(0xffffffffu, r1, 1);
      R2 += r2 + __shfl_xor_sync(0xffffffffu, r2, 1);
    }
  }
  if (half==0){
    g_r1[(size_t)bh*N_ + mg] = R1;
    g_r2[(size_t)bh*N_ + mg] = R2;
  }
}

// ---------------- A = r @ V (per batch, concat heads) ----------------
__global__ __launch_bounds__(768) void k_matvec(){
  int b = blockIdx.x, f = threadIdx.x, h = f >> 6;
  int m0 = blockIdx.y*64;
  const float* r1 = g_r1 + ((size_t)b*NH_+h)*N_;
  const float* r2 = g_r2 + ((size_t)b*NH_+h)*N_;
  float a1=0.f, a2=0.f;
  for (int m=m0; m<m0+64; m++){
    float vv = g_Vb[((size_t)b*N_+m)*H_+f];
    a1 += r1[m]*vv; a2 += r2[m]*vv;
  }
  atomicAdd(&g_A1[b*H_+f], a1);
  atomicAdd(&g_A2[b*H_+f], a2);
}

// ---------------- final projections + broadcast ----------------
__global__ __launch_bounds__(768) void k_final(const float* __restrict__ Wo, const float* __restrict__ bo,
                                               const float* __restrict__ Wa, const float* __restrict__ ba){
  int b = blockIdx.x, o = threadIdx.x;
  __shared__ float u1s[H_], u2s[H_];
  const float* w = Wo + (size_t)o*H_;
  const float* A1 = g_A1 + b*H_;
  const float* A2 = g_A2 + b*H_;
  float u1 = bo[o], u2 = bo[o];
  for (int i=0;i<H_;i++){ u1 += w[i]*A1[i]; u2 += w[i]*A2[i]; }
  u1s[o] = u1; u2s[o] = u2;
  __syncthreads();
  const float* wa = Wa + (size_t)o*2*H_;
  float p = ba[o];
  for (int i=0;i<H_;i++) p += wa[i]*u1s[i] + wa[H_+i]*u2s[i];
  g_pm[b*H_+o] = p;
}

__global__ void k_bcast(float* __restrict__ out){
  int idx = blockIdx.x*blockDim.x + threadIdx.x;
  if (idx >= B_*N_*H_) return;
  int f = idx % H_;
  int b = idx / (N_*H_);
  out[idx] = g_pm[b*H_+f];
}

// ---------------- launch ----------------
extern "C" void kernel_launch(void* const* d_in, const int* in_sizes, int n_in,
                              void* d_out, int out_size){
  (void)in_sizes; (void)n_in; (void)out_size;
  const float* x      = (const float*)d_in[0];
  const float* W_var  = (const float*)d_in[3];
  const float* b_var  = (const float*)d_in[4];
  const float* W_sym  = (const float*)d_in[5];
  const float* b_sym  = (const float*)d_in[6];
  const float* W_sc   = (const float*)d_in[7];
  const float* b_scb  = (const float*)d_in[8];
  const float* W_cr   = (const float*)d_in[9];
  const float* b_cr   = (const float*)d_in[10];
  const float* W_atom = (const float*)d_in[11];
  const float* b_atom = (const float*)d_in[12];
  const float* W_q    = (const float*)d_in[13];
  const float* b_q    = (const float*)d_in[14];
  const float* W_k    = (const float*)d_in[15];
  const float* b_k    = (const float*)d_in[16];
  const float* W_v    = (const float*)d_in[17];
  const float* b_v    = (const float*)d_in[18];
  const float* W_o    = (const float*)d_in[19];
  const float* b_o    = (const float*)d_in[20];
  const int*   pp     = (const int*)d_in[21];
  const int*   occ    = (const int*)d_in[24];
  float* out = (float*)d_out;

  float *p_Q, *p_K, *p_V;
  cudaGetSymbolAddress((void**)&p_Q, g_Qb);
  cudaGetSymbolAddress((void**)&p_K, g_Kb);
  cudaGetSymbolAddress((void**)&p_V, g_Vb);

  static bool attr_done = false;
  if (!attr_done){
    cudaFuncSetAttribute(k_attn1, cudaFuncAttributeMaxDynamicSharedMemorySize, 2*128*PADC*4);
    cudaFuncSetAttribute(k_attn2, cudaFuncAttributeMaxDynamicSharedMemorySize, 2*128*PADC*4);
    attr_done = true;
  }

  k_init<<<(B_*N_+255)/256, 256>>>(b_scb);

  dim3 gp(H_/128, (B_*N_)/128);
  k_gemm_tc<true, true ><<<gp,256>>>(x, W_var, b_var, nullptr, 1.f,    W_sc, 0,  pp);
  k_gemm_tc<false,true ><<<gp,256>>>(x, W_sym, b_sym, nullptr, 1.f,    W_sc, H_, nullptr);
  k_gemm_tc<false,false><<<gp,256>>>(x, W_q,   b_q,   p_Q,     0.125f, nullptr, 0, nullptr);
  k_gemm_tc<false,false><<<gp,256>>>(x, W_k,   b_k,   p_K,     1.f,    nullptr, 0, nullptr);
  k_gemm_tc<false,false><<<gp,256>>>(x, W_v,   b_v,   p_V,     1.f,    nullptr, 0, nullptr);

  k_cross<<<B_*M_, 128>>>(x, W_cr, b_cr, occ);
  k_band<<<(B_*N_+255)/256, 256>>>(pp);
  k_sumw<<<B_, 1024>>>();
  k_coef<<<(B_*N_+255)/256, 256>>>(pp);

  dim3 ga(B_*NH_, N_/128);
  k_attn1<<<ga, 256, 2*128*PADC*4>>>();
  k_w<<<(B_*NH_*N_+255)/256, 256>>>();
  k_attn2<<<ga, 256, 2*128*PADC*4>>>();

  dim3 gmv(B_, 16);
  k_matvec<<<gmv, 768>>>();
  k_final<<<B_, 768>>>(W_o, b_o, W_atom, b_atom);
  k_bcast<<<(B_*N_*H_+255)/256, 256>>>(out);
}

// round 4
// speedup vs baseline: 1.9796x; 1.4009x over previous
#include <cuda_runtime.h>
#include <mma.h>
#include <cstdint>
using namespace nvcuda;

#define B_ 8
#define N_ 1024
#define H_ 768
#define NH_ 12
#define M_ 256
#define ST 68   // smem row stride (floats): 68 mod 32 = 4 -> conflict-free quad access

// ---------------- scratch ----------------
__device__ float g_Qb[B_*N_*H_];
__device__ float g_Kb[B_*N_*H_];
__device__ float g_Vb[B_*N_*H_];
__device__ float g_sc[B_*N_];
__device__ float g_vg2[B_*N_];
__device__ float g_ab[B_*N_];
__device__ float g_dg[B_*N_];
__device__ float g_wt[B_*N_];
__device__ float g_sumw[B_];
__device__ float g_c1[B_*N_];
__device__ float g_c2[B_*N_];
__device__ float g_Z[B_*NH_*N_];
__device__ float g_r1[B_*NH_*N_];
__device__ float g_r2[B_*NH_*N_];
__device__ float g_A1[B_*H_];
__device__ float g_A2[B_*H_];
__device__ float g_pm[B_*H_];

__device__ __forceinline__ bool d_pred(const int* P, int i){ return P[i]==1; }
__device__ __forceinline__ bool d_single(const int* P, int i){ return (i==0) || (i>=2 && P[i-2]==1); }
__device__ __forceinline__ float d_lrelu(float t){ return t >= 0.f ? t : 0.02f*t; }
__device__ __forceinline__ float tf32r(float x){ return wmma::__float_to_tf32(x); }

// m16n8k8 tf32 mma.sync (PTX-documented fragment layout)
__device__ __forceinline__ void mma8(float c[4], const uint32_t a[4], uint32_t b0, uint32_t b1){
  asm volatile(
    "mma.sync.aligned.m16n8k8.row.col.f32.tf32.tf32.f32 "
    "{%0,%1,%2,%3}, {%4,%5,%6,%7}, {%8,%9}, {%0,%1,%2,%3};\n"
    : "+f"(c[0]), "+f"(c[1]), "+f"(c[2]), "+f"(c[3])
    : "r"(a[0]), "r"(a[1]), "r"(a[2]), "r"(a[3]), "r"(b0), "r"(b1));
}

// 8-warp 128x128x64 MMA micro-kernel: warp (wr,wc) covers rows wr*32..+31, cols wc*64..+63
__device__ __forceinline__ void mma_tile(const float* As, const float* Bs,
                                         float c[2][8][4], int wr, int wc, int lane){
  #pragma unroll
  for (int k8=0;k8<8;k8++){
    uint32_t a[2][4];
    int ar = wr*32 + (lane>>2);
    int ac = k8*8 + (lane&3);
    #pragma unroll
    for (int rf=0; rf<2; rf++){
      const float* Ab = As + (ar + rf*16)*ST;
      a[rf][0]=__float_as_uint(Ab[ac]);
      a[rf][1]=__float_as_uint(Ab[8*ST+ac]);
      a[rf][2]=__float_as_uint(Ab[ac+4]);
      a[rf][3]=__float_as_uint(Ab[8*ST+ac+4]);
    }
    #pragma unroll
    for (int nf=0;nf<8;nf++){
      int br = wc*64 + nf*8 + (lane>>2);
      uint32_t b0=__float_as_uint(Bs[br*ST + k8*8 + (lane&3)]);
      uint32_t b1=__float_as_uint(Bs[br*ST + k8*8 + (lane&3)+4]);
      mma8(c[0][nf], a[0], b0, b1);
      mma8(c[1][nf], a[1], b0, b1);
    }
  }
}

// ---------------- init ----------------
__global__ void k_init(const float* __restrict__ bsc){
  int i = blockIdx.x*blockDim.x + threadIdx.x;
  if (i < B_*N_){ g_vg2[i] = 0.f; g_sc[i] = bsc[0]; }
  if (i < B_*H_){ g_A1[i]=0.f; g_A2[i]=0.f; }
  if (i < B_*NH_*N_){ g_Z[i]=0.f; g_r1[i]=0.f; g_r2[i]=0.f; }
}

// ---------------- merged projections: z = 0:var(score) 1:sym(score) 2:Q 3:K 4:V ----------------
__global__ __launch_bounds__(256,2) void k_proj(
    const float* __restrict__ x,
    const float* __restrict__ W_var, const float* __restrict__ b_var,
    const float* __restrict__ W_sym, const float* __restrict__ b_sym,
    const float* __restrict__ W_q,   const float* __restrict__ b_q,
    const float* __restrict__ W_k,   const float* __restrict__ b_k,
    const float* __restrict__ W_v,   const float* __restrict__ b_v,
    const float* __restrict__ Wsc, const int* __restrict__ pp,
    float* __restrict__ Qb, float* __restrict__ Kb, float* __restrict__ Vb){
  extern __shared__ float sm[];
  float* As = sm;             // 128*ST
  float* Bs = sm + 128*ST;
  int mode = blockIdx.z;
  const float* W; const float* bias; float* C=nullptr; float alpha=1.f;
  const float* wsc=nullptr; bool avg=false;
  switch(mode){
    case 0: W=W_var; bias=b_var; wsc=Wsc;     avg=true; break;
    case 1: W=W_sym; bias=b_sym; wsc=Wsc+H_;  break;
    case 2: W=W_q;   bias=b_q;   C=Qb; alpha=0.125f; break;
    case 3: W=W_k;   bias=b_k;   C=Kb; break;
    default:W=W_v;   bias=b_v;   C=Vb; break;
  }
  int tid=threadIdx.x, lane=tid&31, wid=tid>>5;
  int wr=wid&3, wc=wid>>2;
  int m0 = blockIdx.y*128, n0 = blockIdx.x*128;
  float c[2][8][4];
  #pragma unroll
  for(int i=0;i<2;i++)
    #pragma unroll
    for(int j=0;j<8;j++){ c[i][j][0]=0;c[i][j][1]=0;c[i][j][2]=0;c[i][j][3]=0; }
  for (int kt=0; kt<12; kt++){
    __syncthreads();
    #pragma unroll
    for (int it=0; it<8; it++){
      int lin = tid + it*256;
      int r = lin>>4, q = (lin&15)*4;
      float4 av;
      if (avg){
        int m = m0 + r;
        int b = m >> 10, n = m & (N_-1);
        bool single = (n==0) || (n>=2 && pp[b*N_+n-2]==1);
        int np = (n+1)&(N_-1), nm = (n+N_-1)&(N_-1);
        float4 xn = *(const float4*)(x + ((size_t)(b<<10)+np)*H_ + kt*64 + q);
        if (single) av = xn;
        else {
          float4 xp = *(const float4*)(x + ((size_t)(b<<10)+nm)*H_ + kt*64 + q);
          av.x=0.5f*(xp.x+xn.x); av.y=0.5f*(xp.y+xn.y); av.z=0.5f*(xp.z+xn.z); av.w=0.5f*(xp.w+xn.w);
        }
      } else {
        av = *(const float4*)(x + (size_t)(m0+r)*H_ + kt*64 + q);
      }
      float4 bv = *(const float4*)(W + (size_t)(n0+r)*H_ + kt*64 + q);
      float* ad = As + r*ST + q;
      ad[0]=tf32r(av.x); ad[1]=tf32r(av.y); ad[2]=tf32r(av.z); ad[3]=tf32r(av.w);
      float* bd = Bs + r*ST + q;
      bd[0]=tf32r(bv.x); bd[1]=tf32r(bv.y); bd[2]=tf32r(bv.z); bd[3]=tf32r(bv.w);
    }
    __syncthreads();
    mma_tile(As, Bs, c, wr, wc, lane);
  }
  if (mode<=1){
    float p[4] = {0,0,0,0};
    #pragma unroll
    for (int rf=0; rf<2; rf++){
      #pragma unroll
      for (int nf=0; nf<8; nf++){
        int col0 = n0 + wc*64 + nf*8 + 2*(lane&3);
        float w0 = wsc[col0], w1 = wsc[col0+1];
        float b0v = bias[col0], b1v = bias[col0+1];
        p[rf*2+0] += tanhf(c[rf][nf][0]+b0v)*w0 + tanhf(c[rf][nf][1]+b1v)*w1;
        p[rf*2+1] += tanhf(c[rf][nf][2]+b0v)*w0 + tanhf(c[rf][nf][3]+b1v)*w1;
      }
    }
    #pragma unroll
    for (int i=0;i<4;i++){
      float v = p[i];
      v += __shfl_xor_sync(0xffffffffu, v, 1);
      v += __shfl_xor_sync(0xffffffffu, v, 2);
      if ((lane&3)==0)
        atomicAdd(&g_sc[m0 + wr*32 + (i>>1)*16 + (lane>>2) + (i&1)*8], v);
    }
  } else {
    #pragma unroll
    for (int rf=0; rf<2; rf++){
      int row = m0 + wr*32 + rf*16 + (lane>>2);
      #pragma unroll
      for (int nf=0; nf<8; nf++){
        int col0 = n0 + wc*64 + nf*8 + 2*(lane&3);
        float2 bv = *(const float2*)(bias + col0);
        float2 o0 = make_float2(alpha*(c[rf][nf][0]+bv.x), alpha*(c[rf][nf][1]+bv.y));
        float2 o1 = make_float2(alpha*(c[rf][nf][2]+bv.x), alpha*(c[rf][nf][3]+bv.y));
        *(float2*)(C + (size_t)row*H_ + col0) = o0;
        *(float2*)(C + (size_t)(row+8)*H_ + col0) = o1;
      }
    }
  }
}

// ---------------- cross scores -> VG^2 diagonal ----------------
__global__ __launch_bounds__(128) void k_cross(const float* __restrict__ x, const float* __restrict__ Wc,
                                               const float* __restrict__ bc, const int* __restrict__ occ){
  int pid = blockIdx.x;
  int b = pid / M_;
  int o0 = occ[pid*2], o1 = occ[pid*2+1];
  const float* x0 = x + ((size_t)b*N_+o0)*H_;
  const float* x1 = x + ((size_t)b*N_+o1)*H_;
  float p = 0.f;
  for (int h=threadIdx.x; h<H_; h+=128) p += 0.5f*(x0[h]+x1[h])*Wc[h];
  for (int o=16;o;o>>=1) p += __shfl_xor_sync(0xffffffffu, p, o);
  __shared__ float red[4];
  if ((threadIdx.x&31)==0) red[threadIdx.x>>5] = p;
  __syncthreads();
  if (threadIdx.x==0){
    float t = d_lrelu(bc[0] + red[0]+red[1]+red[2]+red[3]);
    atomicAdd(&g_vg2[b*N_+o0], t*t);
    atomicAdd(&g_vg2[b*N_+o1], t*t);
  }
}

// ---------------- AG band + node weights ----------------
__global__ void k_band(const int* __restrict__ pp){
  int idx = blockIdx.x*blockDim.x + threadIdx.x;
  if (idx >= B_*N_) return;
  int b = idx >> 10, n = idx & (N_-1);
  const int* P = pp + b*N_;
  const float* s = g_sc + b*N_;
  float a = 0.f;
  if (n < N_-1){
    float sl1 = d_pred(P,n+1) ? d_lrelu(s[n+1]) : 0.f;
    bool up0 = d_pred(P,n) && (n<=1 || !d_single(P,n));
    float su0 = up0 ? d_lrelu(s[n]) : 0.f;
    a = sl1 + su0;
  }
  g_ab[idx] = a;
  bool up = d_pred(P,n) && (n<=1 || !d_single(P,n));
  bool tr = up && (n>=1);
  g_wt[idx] = d_pred(P,n) ? (tr?3.f:2.f) : 0.f;
}

__global__ __launch_bounds__(1024) void k_sumw(){
  int b = blockIdx.x;
  float v = g_wt[b*N_ + threadIdx.x];
  for (int o=16;o;o>>=1) v += __shfl_xor_sync(0xffffffffu, v, o);
  __shared__ float red[32];
  if ((threadIdx.x&31)==0) red[threadIdx.x>>5] = v;
  __syncthreads();
  if (threadIdx.x < 32){
    float t = red[threadIdx.x];
    for (int o=16;o;o>>=1) t += __shfl_xor_sync(0xffffffffu, t, o);
    if (threadIdx.x==0) g_sumw[b] = t;
  }
}

__global__ void k_coef(const int* __restrict__ pp){
  int idx = blockIdx.x*blockDim.x + threadIdx.x;
  if (idx >= B_*N_) return;
  int b = idx >> 10, n = idx & (N_-1);
  const int* P = pp + b*N_;
  float am1 = (n>=1) ? g_ab[b*N_+n-1] : 0.f;
  float an = g_ab[idx];
  g_dg[idx] = 0.8f*(am1*am1 + an*an) + g_vg2[idx];
  float sw = g_sumw[b];
  int nm = (n+N_-1)&(N_-1), np = (n+1)&(N_-1);
  float c1 = g_wt[b*N_+nm]*(d_single(P,nm)?1.f:0.5f)
           + g_wt[b*N_+np]*(d_single(P,np)?0.f:0.5f);
  g_c1[idx] = c1 / sw;
  g_c2[idx] = g_wt[idx] / sw;
}

// ---------------- attention pass 1: Z[bh][n] = sum_m exp(S[n,m]+bias) ----------------
__global__ __launch_bounds__(256,2) void k_attn1(){
  extern __shared__ float sm[];
  float* Qs = sm;                    // 128*ST (resident Q rows)
  float* Ks = sm + 128*ST;           // 128*ST (streamed K tile)
  float* rowp = sm + 2*128*ST;       // 5*128 band params, idx = d+2
  int tid=threadIdx.x, lane=tid&31, wid=tid>>5;
  int wr=wid&3, wc=wid>>2;
  int bh=blockIdx.x, b=bh/NH_, h=bh-b*NH_;
  int n0=blockIdx.y*128;
  const float* Q = g_Qb + (size_t)b*N_*H_ + h*64;
  const float* K = g_Kb + (size_t)b*N_*H_ + h*64;
  #pragma unroll
  for (int it=0; it<8; it++){
    int lin = tid + it*256;
    int r = lin>>4, q = (lin&15)*4;
    float4 v = *(const float4*)(Q + (size_t)(n0+r)*H_ + q);
    float* d = Qs + r*ST + q;
    d[0]=tf32r(v.x); d[1]=tf32r(v.y); d[2]=tf32r(v.z); d[3]=tf32r(v.w);
  }
  if (tid < 128){
    int n = n0 + tid;
    const float* ab = g_ab + b*N_;
    float anm2=(n>=2)?ab[n-2]:0.f, anm1=(n>=1)?ab[n-1]:0.f;
    float an=ab[n], anp1=(n<N_-1)?ab[n+1]:0.f;
    rowp[0*128+tid]=0.8f*anm2*anm1;
    rowp[1*128+tid]=0.2f*anm1;
    rowp[2*128+tid]=g_dg[b*N_+n];
    rowp[3*128+tid]=0.2f*an;
    rowp[4*128+tid]=0.8f*an*anp1;
  }
  float z[4]={0,0,0,0};
  for (int mt=0; mt<8; mt++){
    __syncthreads();
    #pragma unroll
    for (int it=0; it<8; it++){
      int lin = tid + it*256;
      int r = lin>>4, q = (lin&15)*4;
      float4 v = *(const float4*)(K + (size_t)(mt*128+r)*H_ + q);
      float* d = Ks + r*ST + q;
      d[0]=tf32r(v.x); d[1]=tf32r(v.y); d[2]=tf32r(v.z); d[3]=tf32r(v.w);
    }
    __syncthreads();
    float c[2][8][4];
    #pragma unroll
    for(int i=0;i<2;i++)
      #pragma unroll
      for(int j=0;j<8;j++){ c[i][j][0]=0;c[i][j][1]=0;c[i][j][2]=0;c[i][j][3]=0; }
    mma_tile(Qs, Ks, c, wr, wc, lane);
    #pragma unroll
    for (int rf=0; rf<2; rf++){
      int lr0 = wr*32 + rf*16 + (lane>>2);       // local row (Q row)
      #pragma unroll
      for (int nf=0; nf<8; nf++){
        int m0c = mt*128 + wc*64 + nf*8 + 2*(lane&3);
        #pragma unroll
        for (int e=0; e<4; e++){
          int hi = e>>1;
          int lr = lr0 + hi*8;
          int m = m0c + (e&1);
          int d = m - (n0 + lr);
          float bias = ((unsigned)(d+2) < 5u) ? rowp[(d+2)*128 + lr] : 0.f;
          z[rf*2+hi] += __expf(c[rf][nf][e] + bias);
        }
      }
    }
  }
  #pragma unroll
  for (int i=0;i<4;i++){
    float v = z[i];
    v += __shfl_xor_sync(0xffffffffu, v, 1);
    v += __shfl_xor_sync(0xffffffffu, v, 2);
    if ((lane&3)==0)
      atomicAdd(&g_Z[(size_t)bh*N_ + n0 + wr*32 + (i>>1)*16 + (lane>>2) + (i&1)*8], v);
  }
}

// ---------------- attention pass 2: r[m] = sum_n (c[n]/Z[n])*exp(S[n,m]+bias) ----------------
__global__ __launch_bounds__(256,2) void k_attn2(){
  extern __shared__ float sm[];
  float* Ks = sm;                    // resident K rows (m)
  float* Qs = sm + 128*ST;           // streamed Q tile (n)
  float* colp = sm + 2*128*ST;       // 7*128: [0..4] band (idx d+2), [5] w1, [6] w2
  int tid=threadIdx.x, lane=tid&31, wid=tid>>5;
  int wr=wid&3, wc=wid>>2;
  int bh=blockIdx.x, b=bh/NH_, h=bh-b*NH_;
  int m0=blockIdx.y*128;
  const float* Q = g_Qb + (size_t)b*N_*H_ + h*64;
  const float* K = g_Kb + (size_t)b*N_*H_ + h*64;
  #pragma unroll
  for (int it=0; it<8; it++){
    int lin = tid + it*256;
    int r = lin>>4, q = (lin&15)*4;
    float4 v = *(const float4*)(K + (size_t)(m0+r)*H_ + q);
    float* d = Ks + r*ST + q;
    d[0]=tf32r(v.x); d[1]=tf32r(v.y); d[2]=tf32r(v.z); d[3]=tf32r(v.w);
  }
  float r1[4]={0,0,0,0}, r2[4]={0,0,0,0};
  for (int nt=0; nt<8; nt++){
    __syncthreads();
    #pragma unroll
    for (int it=0; it<8; it++){
      int lin = tid + it*256;
      int r = lin>>4, q = (lin&15)*4;
      float4 v = *(const float4*)(Q + (size_t)(nt*128+r)*H_ + q);
      float* d = Qs + r*ST + q;
      d[0]=tf32r(v.x); d[1]=tf32r(v.y); d[2]=tf32r(v.z); d[3]=tf32r(v.w);
    }
    if (tid < 128){
      int n = nt*128 + tid;
      const float* ab = g_ab + b*N_;
      float anm2=(n>=2)?ab[n-2]:0.f, anm1=(n>=1)?ab[n-1]:0.f;
      float an=ab[n], anp1=(n<N_-1)?ab[n+1]:0.f;
      colp[0*128+tid]=0.8f*anm2*anm1;
      colp[1*128+tid]=0.2f*anm1;
      colp[2*128+tid]=g_dg[b*N_+n];
      colp[3*128+tid]=0.2f*an;
      colp[4*128+tid]=0.8f*an*anp1;
      float iz = 1.f / g_Z[(size_t)bh*N_ + n];
      colp[5*128+tid]=g_c1[b*N_+n]*iz;
      colp[6*128+tid]=g_c2[b*N_+n]*iz;
    }
    __syncthreads();
    float c[2][8][4];
    #pragma unroll
    for(int i=0;i<2;i++)
      #pragma unroll
      for(int j=0;j<8;j++){ c[i][j][0]=0;c[i][j][1]=0;c[i][j][2]=0;c[i][j][3]=0; }
    mma_tile(Ks, Qs, c, wr, wc, lane);
    #pragma unroll
    for (int rf=0; rf<2; rf++){
      int mr0 = m0 + wr*32 + rf*16 + (lane>>2);   // global m row
      #pragma unroll
      for (int nf=0; nf<8; nf++){
        int lc0 = wc*64 + nf*8 + 2*(lane&3);      // local col within tile
        float w1a = colp[5*128+lc0], w1b = colp[5*128+lc0+1];
        float w2a = colp[6*128+lc0], w2b = colp[6*128+lc0+1];
        #pragma unroll
        for (int e=0; e<4; e++){
          int hi = e>>1;
          int lc = lc0 + (e&1);
          int n = nt*128 + lc;
          int d = (mr0 + hi*8) - n;
          float bias = ((unsigned)(d+2) < 5u) ? colp[(d+2)*128 + lc] : 0.f;
          float P = __expf(c[rf][nf][e] + bias);
          r1[rf*2+hi] += ((e&1)? w1b : w1a) * P;
          r2[rf*2+hi] += ((e&1)? w2b : w2a) * P;
        }
      }
    }
  }
  #pragma unroll
  for (int i=0;i<4;i++){
    float v1 = r1[i], v2 = r2[i];
    v1 += __shfl_xor_sync(0xffffffffu, v1, 1);
    v1 += __shfl_xor_sync(0xffffffffu, v1, 2);
    v2 += __shfl_xor_sync(0xffffffffu, v2, 1);
    v2 += __shfl_xor_sync(0xffffffffu, v2, 2);
    if ((lane&3)==0){
      size_t o = (size_t)bh*N_ + m0 + wr*32 + (i>>1)*16 + (lane>>2) + (i&1)*8;
      atomicAdd(&g_r1[o], v1);
      atomicAdd(&g_r2[o], v2);
    }
  }
}

// ---------------- A = r @ V ----------------
__global__ __launch_bounds__(768) void k_matvec(){
  int b = blockIdx.x, f = threadIdx.x, h = f >> 6;
  int m0 = blockIdx.y*64;
  const float* r1 = g_r1 + ((size_t)b*NH_+h)*N_;
  const float* r2 = g_r2 + ((size_t)b*NH_+h)*N_;
  float a1=0.f, a2=0.f;
  for (int m=m0; m<m0+64; m++){
    float vv = g_Vb[((size_t)b*N_+m)*H_+f];
    a1 += r1[m]*vv; a2 += r2[m]*vv;
  }
  atomicAdd(&g_A1[b*H_+f], a1);
  atomicAdd(&g_A2[b*H_+f], a2);
}

// ---------------- final projections + broadcast ----------------
__global__ __launch_bounds__(768) void k_final(const float* __restrict__ Wo, const float* __restrict__ bo,
                                               const float* __restrict__ Wa, const float* __restrict__ ba){
  int b = blockIdx.x, o = threadIdx.x;
  __shared__ float u1s[H_], u2s[H_];
  const float* w = Wo + (size_t)o*H_;
  const float* A1 = g_A1 + b*H_;
  const float* A2 = g_A2 + b*H_;
  float u1 = bo[o], u2 = bo[o];
  for (int i=0;i<H_;i++){ u1 += w[i]*A1[i]; u2 += w[i]*A2[i]; }
  u1s[o] = u1; u2s[o] = u2;
  __syncthreads();
  const float* wa = Wa + (size_t)o*2*H_;
  float p = ba[o];
  for (int i=0;i<H_;i++) p += wa[i]*u1s[i] + wa[H_+i]*u2s[i];
  g_pm[b*H_+o] = p;
}

__global__ void k_bcast(float* __restrict__ out){
  int idx = blockIdx.x*blockDim.x + threadIdx.x;
  if (idx >= B_*N_*H_) return;
  int f = idx % H_;
  int b = idx / (N_*H_);
  out[idx] = g_pm[b*H_+f];
}

// ---------------- launch ----------------
extern "C" void kernel_launch(void* const* d_in, const int* in_sizes, int n_in,
                              void* d_out, int out_size){
  (void)in_sizes; (void)n_in; (void)out_size;
  const float* x      = (const float*)d_in[0];
  const float* W_var  = (const float*)d_in[3];
  const float* b_var  = (const float*)d_in[4];
  const float* W_sym  = (const float*)d_in[5];
  const float* b_sym  = (const float*)d_in[6];
  const float* W_sc   = (const float*)d_in[7];
  const float* b_scb  = (const float*)d_in[8];
  const float* W_cr   = (const float*)d_in[9];
  const float* b_cr   = (const float*)d_in[10];
  const float* W_atom = (const float*)d_in[11];
  const float* b_atom = (const float*)d_in[12];
  const float* W_q    = (const float*)d_in[13];
  const float* b_q    = (const float*)d_in[14];
  const float* W_k    = (const float*)d_in[15];
  const float* b_k    = (const float*)d_in[16];
  const float* W_v    = (const float*)d_in[17];
  const float* b_v    = (const float*)d_in[18];
  const float* W_o    = (const float*)d_in[19];
  const float* b_o    = (const float*)d_in[20];
  const int*   pp     = (const int*)d_in[21];
  const int*   occ    = (const int*)d_in[24];
  float* out = (float*)d_out;

  float *p_Q, *p_K, *p_V;
  cudaGetSymbolAddress((void**)&p_Q, g_Qb);
  cudaGetSymbolAddress((void**)&p_K, g_Kb);
  cudaGetSymbolAddress((void**)&p_V, g_Vb);

  const int PROJ_SMEM  = (2*128*ST)*4;
  const int ATTN1_SMEM = (2*128*ST + 5*128)*4;
  const int ATTN2_SMEM = (2*128*ST + 7*128)*4;
  static bool attr_done = false;
  if (!attr_done){
    cudaFuncSetAttribute(k_proj,  cudaFuncAttributeMaxDynamicSharedMemorySize, PROJ_SMEM);
    cudaFuncSetAttribute(k_attn1, cudaFuncAttributeMaxDynamicSharedMemorySize, ATTN1_SMEM);
    cudaFuncSetAttribute(k_attn2, cudaFuncAttributeMaxDynamicSharedMemorySize, ATTN2_SMEM);
    attr_done = true;
  }

  k_init<<<(B_*NH_*N_+255)/256, 256>>>(b_scb);

  dim3 gp(H_/128, (B_*N_)/128, 5);
  k_proj<<<gp, 256, PROJ_SMEM>>>(x, W_var,b_var, W_sym,b_sym, W_q,b_q, W_k,b_k, W_v,b_v,
                                 W_sc, pp, p_Q, p_K, p_V);

  k_cross<<<B_*M_, 128>>>(x, W_cr, b_cr, occ);
  k_band<<<(B_*N_+255)/256, 256>>>(pp);
  k_sumw<<<B_, 1024>>>();
  k_coef<<<(B_*N_+255)/256, 256>>>(pp);

  dim3 ga(B_*NH_, N_/128);
  k_attn1<<<ga, 256, ATTN1_SMEM>>>();
  k_attn2<<<ga, 256, ATTN2_SMEM>>>();

  dim3 gmv(B_, 16);
  k_matvec<<<gmv, 768>>>();
  k_final<<<B_, 768>>>(W_o, b_o, W_atom, b_atom);
  k_bcast<<<(B_*N_*H_+255)/256, 256>>>(out);
}

// round 5
// speedup vs baseline: 2.1794x; 1.1010x over previous
#include <cuda_runtime.h>
#include <mma.h>
#include <cstdint>
using namespace nvcuda;

#define B_ 8
#define N_ 1024
#define H_ 768
#define NH_ 12
#define M_ 256
#define ST 68    // attn smem row stride (floats)
#define STP 36   // proj smem row stride (k-tile 32 + pad 4)
#define KT 32
#define NKT 24

// ---------------- scratch ----------------
__device__ float g_xr[B_*N_*H_];       // tf32-rounded x
__device__ float g_Wr[5*H_*H_];        // tf32-rounded W: var,sym,q,k,v
__device__ float g_Qb[B_*N_*H_];
__device__ float g_Kb[B_*N_*H_];
__device__ float g_Vb[B_*N_*H_];
__device__ float g_sc[B_*N_];
__device__ float g_vg2[B_*N_];
__device__ float g_ab[B_*N_];
__device__ float g_dg[B_*N_];
__device__ float g_wt[B_*N_];
__device__ float g_sumw[B_];
__device__ float g_c1[B_*N_];
__device__ float g_c2[B_*N_];
__device__ float g_Z[B_*NH_*N_];
__device__ float g_r1[B_*NH_*N_];
__device__ float g_r2[B_*NH_*N_];
__device__ float g_A1[B_*H_];
__device__ float g_A2[B_*H_];
__device__ float g_pm[B_*H_];

__device__ __forceinline__ bool d_pred(const int* P, int i){ return P[i]==1; }
__device__ __forceinline__ bool d_single(const int* P, int i){ return (i==0) || (i>=2 && P[i-2]==1); }
__device__ __forceinline__ float d_lrelu(float t){ return t >= 0.f ? t : 0.02f*t; }
__device__ __forceinline__ float tf32r(float x){ return wmma::__float_to_tf32(x); }

// ---------------- cp.async helpers ----------------
__device__ __forceinline__ void cpa16(float* s, const float* g){
  asm volatile("cp.async.cg.shared.global [%0], [%1], 16;\n"
               :: "r"((uint32_t)__cvta_generic_to_shared(s)), "l"(g));
}
__device__ __forceinline__ void cp_commit(){ asm volatile("cp.async.commit_group;\n"); }
__device__ __forceinline__ void cp_wait1(){ asm volatile("cp.async.wait_group 1;\n"); }
__device__ __forceinline__ void cp_wait0(){ asm volatile("cp.async.wait_group 0;\n"); }

// ---------------- m16n8k8 tf32 mma.sync ----------------
__device__ __forceinline__ void mma8(float c[4], const uint32_t a[4], uint32_t b0, uint32_t b1){
  asm volatile(
    "mma.sync.aligned.m16n8k8.row.col.f32.tf32.tf32.f32 "
    "{%0,%1,%2,%3}, {%4,%5,%6,%7}, {%8,%9}, {%0,%1,%2,%3};\n"
    : "+f"(c[0]), "+f"(c[1]), "+f"(c[2]), "+f"(c[3])
    : "r"(a[0]), "r"(a[1]), "r"(a[2]), "r"(a[3]), "r"(b0), "r"(b1));
}

// 8-warp 128x128xK MMA micro-kernel (K = K8*8), warp (wr,wc): rows wr*32..+31, cols wc*64..+63
template<int STRIDE, int K8>
__device__ __forceinline__ void mma_tile(const float* As, const float* Bs,
                                         float c[2][8][4], int wr, int wc, int lane){
  #pragma unroll
  for (int k8=0;k8<K8;k8++){
    uint32_t a[2][4];
    int ar = wr*32 + (lane>>2);
    int ac = k8*8 + (lane&3);
    #pragma unroll
    for (int rf=0; rf<2; rf++){
      const float* Ab = As + (ar + rf*16)*STRIDE;
      a[rf][0]=__float_as_uint(Ab[ac]);
      a[rf][1]=__float_as_uint(Ab[8*STRIDE+ac]);
      a[rf][2]=__float_as_uint(Ab[ac+4]);
      a[rf][3]=__float_as_uint(Ab[8*STRIDE+ac+4]);
    }
    #pragma unroll
    for (int nf=0;nf<8;nf++){
      int br = wc*64 + nf*8 + (lane>>2);
      uint32_t b0=__float_as_uint(Bs[br*STRIDE + k8*8 + (lane&3)]);
      uint32_t b1=__float_as_uint(Bs[br*STRIDE + k8*8 + (lane&3)+4]);
      mma8(c[0][nf], a[0], b0, b1);
      mma8(c[1][nf], a[1], b0, b1);
    }
  }
}

// ---------------- init ----------------
__global__ void k_init(const float* __restrict__ bsc){
  int i = blockIdx.x*blockDim.x + threadIdx.x;
  if (i < B_*N_){ g_vg2[i] = 0.f; g_sc[i] = bsc[0]; }
  if (i < B_*H_){ g_A1[i]=0.f; g_A2[i]=0.f; }
  if (i < B_*NH_*N_){ g_Z[i]=0.f; g_r1[i]=0.f; g_r2[i]=0.f; }
}

// ---------------- pre-round x and weights to tf32 ----------------
__global__ void k_preconv(const float* __restrict__ x,
                          const float* __restrict__ W0, const float* __restrict__ W1,
                          const float* __restrict__ W2, const float* __restrict__ W3,
                          const float* __restrict__ W4){
  const int XT4 = B_*N_*H_/4;
  const int WT4 = H_*H_/4;
  int i = blockIdx.x*blockDim.x + threadIdx.x;
  if (i < XT4){
    float4 v = ((const float4*)x)[i];
    v.x=tf32r(v.x); v.y=tf32r(v.y); v.z=tf32r(v.z); v.w=tf32r(v.w);
    ((float4*)g_xr)[i]=v;
  } else {
    int j = i - XT4;
    if (j < 5*WT4){
      int w = j / WT4, o = j - w*WT4;
      const float* src = (w==0)?W0:(w==1)?W1:(w==2)?W2:(w==3)?W3:W4;
      float4 v = ((const float4*)src)[o];
      v.x=tf32r(v.x); v.y=tf32r(v.y); v.z=tf32r(v.z); v.w=tf32r(v.w);
      ((float4*)(g_Wr + (size_t)w*H_*H_))[o]=v;
    }
  }
}

// ---------------- mode-0 A staging: rolled neighbor average of tf32 x ----------------
__device__ __forceinline__ void stage_avg(float* dst, int m0, int kc, const int* __restrict__ pp, int tid){
  #pragma unroll
  for (int i=0;i<4;i++){
    int lin = tid + i*256;
    int r = lin>>3, q = (lin&7)*4;
    int m = m0 + r, b = m>>10, n = m&(N_-1);
    bool single = (n==0) || (n>=2 && pp[b*N_+n-2]==1);
    int np = (n+1)&(N_-1), nm = (n+N_-1)&(N_-1);
    const float* base = g_xr + ((size_t)(b<<10))*H_ + kc + q;
    float4 xn = *(const float4*)(base + (size_t)np*H_);
    float4 v;
    if (single) v = xn;
    else {
      float4 xp = *(const float4*)(base + (size_t)nm*H_);
      v.x=0.5f*(xp.x+xn.x); v.y=0.5f*(xp.y+xn.y); v.z=0.5f*(xp.z+xn.z); v.w=0.5f*(xp.w+xn.w);
    }
    *(float4*)(dst + r*STP + q) = v;
  }
}

// ---------------- merged projections: z = 0:var(score) 1:sym(score) 2:Q 3:K 4:V ----------------
__global__ __launch_bounds__(256,2) void k_proj(
    const float* __restrict__ b_var, const float* __restrict__ b_sym,
    const float* __restrict__ b_q, const float* __restrict__ b_k, const float* __restrict__ b_v,
    const float* __restrict__ Wsc, const int* __restrict__ pp,
    float* __restrict__ Qb, float* __restrict__ Kb, float* __restrict__ Vb){
  extern __shared__ float sm[];
  float* Ab[2] = { sm,             sm + 128*STP };
  float* Bb[2] = { sm + 2*128*STP, sm + 3*128*STP };
  int mode = blockIdx.z;
  const float* W = g_Wr + (size_t)mode*H_*H_;
  const float* bias; float* C=nullptr; float alpha=1.f; const float* wsc=nullptr;
  switch(mode){
    case 0: bias=b_var; wsc=Wsc;    break;
    case 1: bias=b_sym; wsc=Wsc+H_; break;
    case 2: bias=b_q;   C=Qb; alpha=0.125f; break;
    case 3: bias=b_k;   C=Kb; break;
    default:bias=b_v;   C=Vb; break;
  }
  int tid=threadIdx.x, lane=tid&31, wid=tid>>5;
  int wr=wid&3, wc=wid>>2;
  int m0 = blockIdx.y*128, n0 = blockIdx.x*128;
  // initial staging of tile 0
  if (mode==0) stage_avg(Ab[0], m0, 0, pp, tid);
  else {
    #pragma unroll
    for (int i=0;i<4;i++){
      int lin=tid+i*256; int r=lin>>3, q=(lin&7)*4;
      cpa16(Ab[0]+r*STP+q, g_xr + (size_t)(m0+r)*H_ + q);
    }
  }
  #pragma unroll
  for (int i=0;i<4;i++){
    int lin=tid+i*256; int r=lin>>3, q=(lin&7)*4;
    cpa16(Bb[0]+r*STP+q, W + (size_t)(n0+r)*H_ + q);
  }
  cp_commit();
  float c[2][8][4];
  #pragma unroll
  for(int i=0;i<2;i++)
    #pragma unroll
    for(int j=0;j<8;j++){ c[i][j][0]=0;c[i][j][1]=0;c[i][j][2]=0;c[i][j][3]=0; }
  for (int kt=0; kt<NKT; kt++){
    int cur=kt&1, nxt=1-cur;
    if (kt+1<NKT){
      if (mode!=0){
        #pragma unroll
        for (int i=0;i<4;i++){
          int lin=tid+i*256; int r=lin>>3, q=(lin&7)*4;
          cpa16(Ab[nxt]+r*STP+q, g_xr + (size_t)(m0+r)*H_ + (kt+1)*KT + q);
        }
      }
      #pragma unroll
      for (int i=0;i<4;i++){
        int lin=tid+i*256; int r=lin>>3, q=(lin&7)*4;
        cpa16(Bb[nxt]+r*STP+q, W + (size_t)(n0+r)*H_ + (kt+1)*KT + q);
      }
      cp_commit();
      cp_wait1();
    } else cp_wait0();
    __syncthreads();
    mma_tile<STP,4>(Ab[cur], Bb[cur], c, wr, wc, lane);
    if (mode==0 && kt+1<NKT) stage_avg(Ab[nxt], m0, (kt+1)*KT, pp, tid);
    __syncthreads();
  }
  if (mode<=1){
    float p[4] = {0,0,0,0};
    #pragma unroll
    for (int rf=0; rf<2; rf++){
      #pragma unroll
      for (int nf=0; nf<8; nf++){
        int col0 = n0 + wc*64 + nf*8 + 2*(lane&3);
        float w0 = wsc[col0], w1 = wsc[col0+1];
        float b0v = bias[col0], b1v = bias[col0+1];
        p[rf*2+0] += tanhf(c[rf][nf][0]+b0v)*w0 + tanhf(c[rf][nf][1]+b1v)*w1;
        p[rf*2+1] += tanhf(c[rf][nf][2]+b0v)*w0 + tanhf(c[rf][nf][3]+b1v)*w1;
      }
    }
    #pragma unroll
    for (int i=0;i<4;i++){
      float v = p[i];
      v += __shfl_xor_sync(0xffffffffu, v, 1);
      v += __shfl_xor_sync(0xffffffffu, v, 2);
      if ((lane&3)==0)
        atomicAdd(&g_sc[m0 + wr*32 + (i>>1)*16 + (lane>>2) + (i&1)*8], v);
    }
  } else {
    #pragma unroll
    for (int rf=0; rf<2; rf++){
      int row = m0 + wr*32 + rf*16 + (lane>>2);
      #pragma unroll
      for (int nf=0; nf<8; nf++){
        int col0 = n0 + wc*64 + nf*8 + 2*(lane&3);
        float2 bv = *(const float2*)(bias + col0);
        float o00 = alpha*(c[rf][nf][0]+bv.x), o01 = alpha*(c[rf][nf][1]+bv.y);
        float o10 = alpha*(c[rf][nf][2]+bv.x), o11 = alpha*(c[rf][nf][3]+bv.y);
        if (mode!=4){ o00=tf32r(o00); o01=tf32r(o01); o10=tf32r(o10); o11=tf32r(o11); }
        *(float2*)(C + (size_t)row*H_ + col0) = make_float2(o00,o01);
        *(float2*)(C + (size_t)(row+8)*H_ + col0) = make_float2(o10,o11);
      }
    }
  }
}

// ---------------- cross scores -> VG^2 diagonal ----------------
__global__ __launch_bounds__(128) void k_cross(const float* __restrict__ x, const float* __restrict__ Wc,
                                               const float* __restrict__ bc, const int* __restrict__ occ){
  int pid = blockIdx.x;
  int b = pid / M_;
  int o0 = occ[pid*2], o1 = occ[pid*2+1];
  const float* x0 = x + ((size_t)b*N_+o0)*H_;
  const float* x1 = x + ((size_t)b*N_+o1)*H_;
  float p = 0.f;
  for (int h=threadIdx.x; h<H_; h+=128) p += 0.5f*(x0[h]+x1[h])*Wc[h];
  for (int o=16;o;o>>=1) p += __shfl_xor_sync(0xffffffffu, p, o);
  __shared__ float red[4];
  if ((threadIdx.x&31)==0) red[threadIdx.x>>5] = p;
  __syncthreads();
  if (threadIdx.x==0){
    float t = d_lrelu(bc[0] + red[0]+red[1]+red[2]+red[3]);
    atomicAdd(&g_vg2[b*N_+o0], t*t);
    atomicAdd(&g_vg2[b*N_+o1], t*t);
  }
}

// ---------------- AG band + node weights ----------------
__global__ void k_band(const int* __restrict__ pp){
  int idx = blockIdx.x*blockDim.x + threadIdx.x;
  if (idx >= B_*N_) return;
  int b = idx >> 10, n = idx & (N_-1);
  const int* P = pp + b*N_;
  const float* s = g_sc + b*N_;
  float a = 0.f;
  if (n < N_-1){
    float sl1 = d_pred(P,n+1) ? d_lrelu(s[n+1]) : 0.f;
    bool up0 = d_pred(P,n) && (n<=1 || !d_single(P,n));
    float su0 = up0 ? d_lrelu(s[n]) : 0.f;
    a = sl1 + su0;
  }
  g_ab[idx] = a;
  bool up = d_pred(P,n) && (n<=1 || !d_single(P,n));
  bool tr = up && (n>=1);
  g_wt[idx] = d_pred(P,n) ? (tr?3.f:2.f) : 0.f;
}

__global__ __launch_bounds__(1024) void k_sumw(){
  int b = blockIdx.x;
  float v = g_wt[b*N_ + threadIdx.x];
  for (int o=16;o;o>>=1) v += __shfl_xor_sync(0xffffffffu, v, o);
  __shared__ float red[32];
  if ((threadIdx.x&31)==0) red[threadIdx.x>>5] = v;
  __syncthreads();
  if (threadIdx.x < 32){
    float t = red[threadIdx.x];
    for (int o=16;o;o>>=1) t += __shfl_xor_sync(0xffffffffu, t, o);
    if (threadIdx.x==0) g_sumw[b] = t;
  }
}

__global__ void k_coef(const int* __restrict__ pp){
  int idx = blockIdx.x*blockDim.x + threadIdx.x;
  if (idx >= B_*N_) return;
  int b = idx >> 10, n = idx & (N_-1);
  const int* P = pp + b*N_;
  float am1 = (n>=1) ? g_ab[b*N_+n-1] : 0.f;
  float an = g_ab[idx];
  g_dg[idx] = 0.8f*(am1*am1 + an*an) + g_vg2[idx];
  float sw = g_sumw[b];
  int nm = (n+N_-1)&(N_-1), np = (n+1)&(N_-1);
  float c1 = g_wt[b*N_+nm]*(d_single(P,nm)?1.f:0.5f)
           + g_wt[b*N_+np]*(d_single(P,np)?0.f:0.5f);
  g_c1[idx] = c1 / sw;
  g_c2[idx] = g_wt[idx] / sw;
}

// ---------------- attention pass 1: Z[bh][n] = sum_m exp(S[n,m]+bias) ----------------
__global__ __launch_bounds__(256,2) void k_attn1(){
  extern __shared__ float sm[];
  float* Qs = sm;                              // resident Q rows
  float* Kb[2] = { sm + 128*ST, sm + 2*128*ST };
  float* rowp = sm + 3*128*ST;                 // 5*128 band params, idx = d+2
  int tid=threadIdx.x, lane=tid&31, wid=tid>>5;
  int wr=wid&3, wc=wid>>2;
  int bh=blockIdx.x, b=bh/NH_, h=bh-b*NH_;
  int n0=blockIdx.y*128;
  const float* Q = g_Qb + (size_t)b*N_*H_ + h*64;
  const float* K = g_Kb + (size_t)b*N_*H_ + h*64;
  #pragma unroll
  for (int it=0; it<8; it++){
    int lin = tid + it*256;
    int r = lin>>4, q = (lin&15)*4;
    cpa16(Qs + r*ST + q, Q + (size_t)(n0+r)*H_ + q);
  }
  #pragma unroll
  for (int it=0; it<8; it++){
    int lin = tid + it*256;
    int r = lin>>4, q = (lin&15)*4;
    cpa16(Kb[0] + r*ST + q, K + (size_t)r*H_ + q);
  }
  cp_commit();
  if (tid < 128){
    int n = n0 + tid;
    const float* ab = g_ab + b*N_;
    float anm2=(n>=2)?ab[n-2]:0.f, anm1=(n>=1)?ab[n-1]:0.f;
    float an=ab[n], anp1=(n<N_-1)?ab[n+1]:0.f;
    rowp[0*128+tid]=0.8f*anm2*anm1;
    rowp[1*128+tid]=0.2f*anm1;
    rowp[2*128+tid]=g_dg[b*N_+n];
    rowp[3*128+tid]=0.2f*an;
    rowp[4*128+tid]=0.8f*an*anp1;
  }
  float z[4]={0,0,0,0};
  for (int mt=0; mt<8; mt++){
    int cur=mt&1;
    if (mt+1<8){
      #pragma unroll
      for (int it=0; it<8; it++){
        int lin = tid + it*256;
        int r = lin>>4, q = (lin&15)*4;
        cpa16(Kb[1-cur] + r*ST + q, K + (size_t)((mt+1)*128+r)*H_ + q);
      }
      cp_commit();
      cp_wait1();
    } else cp_wait0();
    __syncthreads();
    float c[2][8][4];
    #pragma unroll
    for(int i=0;i<2;i++)
      #pragma unroll
      for(int j=0;j<8;j++){ c[i][j][0]=0;c[i][j][1]=0;c[i][j][2]=0;c[i][j][3]=0; }
    mma_tile<ST,8>(Qs, Kb[cur], c, wr, wc, lane);
    #pragma unroll
    for (int rf=0; rf<2; rf++){
      int lr0 = wr*32 + rf*16 + (lane>>2);
      #pragma unroll
      for (int nf=0; nf<8; nf++){
        int m0c = mt*128 + wc*64 + nf*8 + 2*(lane&3);
        #pragma unroll
        for (int e=0; e<4; e++){
          int hi = e>>1;
          int lr = lr0 + hi*8;
          int m = m0c + (e&1);
          int d = m - (n0 + lr);
          float bias = ((unsigned)(d+2) < 5u) ? rowp[(d+2)*128 + lr] : 0.f;
          z[rf*2+hi] += __expf(c[rf][nf][e] + bias);
        }
      }
    }
    __syncthreads();
  }
  #pragma unroll
  for (int i=0;i<4;i++){
    float v = z[i];
    v += __shfl_xor_sync(0xffffffffu, v, 1);
    v += __shfl_xor_sync(0xffffffffu, v, 2);
    if ((lane&3)==0)
      atomicAdd(&g_Z[(size_t)bh*N_ + n0 + wr*32 + (i>>1)*16 + (lane>>2) + (i&1)*8], v);
  }
}

// ---------------- attention pass 2: r[m] = sum_n (c[n]/Z[n])*exp(S[n,m]+bias) ----------------
__global__ __launch_bounds__(256,2) void k_attn2(){
  extern __shared__ float sm[];
  float* Ks = sm;                              // resident K rows (m)
  float* Qb2[2] = { sm + 128*ST, sm + 2*128*ST };
  float* colp = sm + 3*128*ST;                 // 7*128
  int tid=threadIdx.x, lane=tid&31, wid=tid>>5;
  int wr=wid&3, wc=wid>>2;
  int bh=blockIdx.x, b=bh/NH_, h=bh-b*NH_;
  int m0=blockIdx.y*128;
  const float* Q = g_Qb + (size_t)b*N_*H_ + h*64;
  const float* K = g_Kb + (size_t)b*N_*H_ + h*64;
  #pragma unroll
  for (int it=0; it<8; it++){
    int lin = tid + it*256;
    int r = lin>>4, q = (lin&15)*4;
    cpa16(Ks + r*ST + q, K + (size_t)(m0+r)*H_ + q);
  }
  #pragma unroll
  for (int it=0; it<8; it++){
    int lin = tid + it*256;
    int r = lin>>4, q = (lin&15)*4;
    cpa16(Qb2[0] + r*ST + q, Q + (size_t)r*H_ + q);
  }
  cp_commit();
  float r1[4]={0,0,0,0}, r2[4]={0,0,0,0};
  for (int nt=0; nt<8; nt++){
    int cur=nt&1;
    if (nt+1<8){
      #pragma unroll
      for (int it=0; it<8; it++){
        int lin = tid + it*256;
        int r = lin>>4, q = (lin&15)*4;
        cpa16(Qb2[1-cur] + r*ST + q, Q + (size_t)((nt+1)*128+r)*H_ + q);
      }
      cp_commit();
    }
    if (tid < 128){
      int n = nt*128 + tid;
      const float* ab = g_ab + b*N_;
      float anm2=(n>=2)?ab[n-2]:0.f, anm1=(n>=1)?ab[n-1]:0.f;
      float an=ab[n], anp1=(n<N_-1)?ab[n+1]:0.f;
      colp[0*128+tid]=0.8f*anm2*anm1;
      colp[1*128+tid]=0.2f*anm1;
      colp[2*128+tid]=g_dg[b*N_+n];
      colp[3*128+tid]=0.2f*an;
      colp[4*128+tid]=0.8f*an*anp1;
      float iz = 1.f / g_Z[(size_t)bh*N_ + n];
      colp[5*128+tid]=g_c1[b*N_+n]*iz;
      colp[6*128+tid]=g_c2[b*N_+n]*iz;
    }
    if (nt+1<8) cp_wait1(); else cp_wait0();
    __syncthreads();
    float c[2][8][4];
    #pragma unroll
    for(int i=0;i<2;i++)
      #pragma unroll
      for(int j=0;j<8;j++){ c[i][j][0]=0;c[i][j][1]=0;c[i][j][2]=0;c[i][j][3]=0; }
    mma_tile<ST,8>(Ks, Qb2[cur], c, wr, wc, lane);
    #pragma unroll
    for (int rf=0; rf<2; rf++){
      int mr0 = m0 + wr*32 + rf*16 + (lane>>2);
      #pragma unroll
      for (int nf=0; nf<8; nf++){
        int lc0 = wc*64 + nf*8 + 2*(lane&3);
        float w1a = colp[5*128+lc0], w1b = colp[5*128+lc0+1];
        float w2a = colp[6*128+lc0], w2b = colp[6*128+lc0+1];
        #pragma unroll
        for (int e=0; e<4; e++){
          int hi = e>>1;
          int lc = lc0 + (e&1);
          int n = nt*128 + lc;
          int d = (mr0 + hi*8) - n;
          float bias = ((unsigned)(d+2) < 5u) ? colp[(d+2)*128 + lc] : 0.f;
          float P = __expf(c[rf][nf][e] + bias);
          r1[rf*2+hi] += ((e&1)? w1b : w1a) * P;
          r2[rf*2+hi] += ((e&1)? w2b : w2a) * P;
        }
      }
    }
    __syncthreads();
  }
  #pragma unroll
  for (int i=0;i<4;i++){
    float v1 = r1[i], v2 = r2[i];
    v1 += __shfl_xor_sync(0xffffffffu, v1, 1);
    v1 += __shfl_xor_sync(0xffffffffu, v1, 2);
    v2 += __shfl_xor_sync(0xffffffffu, v2, 1);
    v2 += __shfl_xor_sync(0xffffffffu, v2, 2);
    if ((lane&3)==0){
      size_t o = (size_t)bh*N_ + m0 + wr*32 + (i>>1)*16 + (lane>>2) + (i&1)*8;
      atomicAdd(&g_r1[o], v1);
      atomicAdd(&g_r2[o], v2);
    }
  }
}

// ---------------- A = r @ V ----------------
__global__ __launch_bounds__(768) void k_matvec(){
  int b = blockIdx.x, f = threadIdx.x, h = f >> 6;
  int m0 = blockIdx.y*64;
  const float* r1 = g_r1 + ((size_t)b*NH_+h)*N_;
  const float* r2 = g_r2 + ((size_t)b*NH_+h)*N_;
  float a1=0.f, a2=0.f;
  for (int m=m0; m<m0+64; m++){
    float vv = g_Vb[((size_t)b*N_+m)*H_+f];
    a1 += r1[m]*vv; a2 += r2[m]*vv;
  }
  atomicAdd(&g_A1[b*H_+f], a1);
  atomicAdd(&g_A2[b*H_+f], a2);
}

// ---------------- final projections + broadcast ----------------
__global__ __launch_bounds__(768) void k_final(const float* __restrict__ Wo, const float* __restrict__ bo,
                                               const float* __restrict__ Wa, const float* __restrict__ ba){
  int b = blockIdx.x, o = threadIdx.x;
  __shared__ float u1s[H_], u2s[H_];
  const float* w = Wo + (size_t)o*H_;
  const float* A1 = g_A1 + b*H_;
  const float* A2 = g_A2 + b*H_;
  float u1 = bo[o], u2 = bo[o];
  for (int i=0;i<H_;i++){ u1 += w[i]*A1[i]; u2 += w[i]*A2[i]; }
  u1s[o] = u1; u2s[o] = u2;
  __syncthreads();
  const float* wa = Wa + (size_t)o*2*H_;
  float p = ba[o];
  for (int i=0;i<H_;i++) p += wa[i]*u1s[i] + wa[H_+i]*u2s[i];
  g_pm[b*H_+o] = p;
}

__global__ void k_bcast(float* __restrict__ out){
  int idx = blockIdx.x*blockDim.x + threadIdx.x;
  if (idx >= B_*N_*H_) return;
  int f = idx % H_;
  int b = idx / (N_*H_);
  out[idx] = g_pm[b*H_+f];
}

// ---------------- launch ----------------
extern "C" void kernel_launch(void* const* d_in, const int* in_sizes, int n_in,
                              void* d_out, int out_size){
  (void)in_sizes; (void)n_in; (void)out_size;
  const float* x      = (const float*)d_in[0];
  const float* W_var  = (const float*)d_in[3];
  const float* b_var  = (const float*)d_in[4];
  const float* W_sym  = (const float*)d_in[5];
  const float* b_sym  = (const float*)d_in[6];
  const float* W_sc   = (const float*)d_in[7];
  const float* b_scb  = (const float*)d_in[8];
  const float* W_cr   = (const float*)d_in[9];
  const float* b_cr   = (const float*)d_in[10];
  const float* W_atom = (const float*)d_in[11];
  const float* b_atom = (const float*)d_in[12];
  const float* W_q    = (const float*)d_in[13];
  const float* b_q    = (const float*)d_in[14];
  const float* W_k    = (const float*)d_in[15];
  const float* b_k    = (const float*)d_in[16];
  const float* W_v    = (const float*)d_in[17];
  const float* b_v    = (const float*)d_in[18];
  const float* W_o    = (const float*)d_in[19];
  const float* b_o    = (const float*)d_in[20];
  const int*   pp     = (const int*)d_in[21];
  const int*   occ    = (const int*)d_in[24];
  float* out = (float*)d_out;

  float *p_Q, *p_K, *p_V;
  cudaGetSymbolAddress((void**)&p_Q, g_Qb);
  cudaGetSymbolAddress((void**)&p_K, g_Kb);
  cudaGetSymbolAddress((void**)&p_V, g_Vb);

  const int PROJ_SMEM  = (4*128*STP)*4;
  const int ATTN1_SMEM = (3*128*ST + 5*128)*4;
  const int ATTN2_SMEM = (3*128*ST + 7*128)*4;
  static bool attr_done = false;
  if (!attr_done){
    cudaFuncSetAttribute(k_proj,  cudaFuncAttributeMaxDynamicSharedMemorySize, PROJ_SMEM);
    cudaFuncSetAttribute(k_attn1, cudaFuncAttributeMaxDynamicSharedMemorySize, ATTN1_SMEM);
    cudaFuncSetAttribute(k_attn2, cudaFuncAttributeMaxDynamicSharedMemorySize, ATTN2_SMEM);
    attr_done = true;
  }

  k_init<<<(B_*NH_*N_+255)/256, 256>>>(b_scb);
  const int PRE4 = B_*N_*H_/4 + 5*H_*H_/4;
  k_preconv<<<(PRE4+255)/256, 256>>>(x, W_var, W_sym, W_q, W_k, W_v);

  dim3 gp(H_/128, (B_*N_)/128, 5);
  k_proj<<<gp, 256, PROJ_SMEM>>>(b_var, b_sym, b_q, b_k, b_v, W_sc, pp, p_Q, p_K, p_V);

  k_cross<<<B_*M_, 128>>>(x, W_cr, b_cr, occ);
  k_band<<<(B_*N_+255)/256, 256>>>(pp);
  k_sumw<<<B_, 1024>>>();
  k_coef<<<(B_*N_+255)/256, 256>>>(pp);

  dim3 ga(B_*NH_, N_/128);
  k_attn1<<<ga, 256, ATTN1_SMEM>>>();
  k_attn2<<<ga, 256, ATTN2_SMEM>>>();

  dim3 gmv(B_, 16);
  k_matvec<<<gmv, 768>>>();
  k_final<<<B_, 768>>>(W_o, b_o, W_atom, b_atom);
  k_bcast<<<(B_*N_*H_+255)/256, 256>>>(out);
}